// round 3
// baseline (speedup 1.0000x reference)
#include <cuda_runtime.h>

#define B_ 32
#define CIN 256
#define CC 64
#define HS 64
#define PS 4096         // 64*64
#define HT 14
#define PT 196          // 14*14
#define NG 32           // groups (2 channels per group)

// ---------------- device scratch (no allocations allowed) ----------------
__device__ float g_s_pre[B_*CC*PS];       // conv1x1(search) pre-GN
__device__ float g_corr[B_*CC*PS];        // global + local correlation
__device__ float g_y_pre[B_*CC*PS];       // conv3x3 pre-GN
__device__ float g_tglobal[B_*CC];        // mean of relu(gn(t)) per (b,c)
__device__ float g_tkernel[B_*CC*49];     // 7x7 pooled template kernel
__device__ float g_part_s[B_*NG*32*2];    // per-(b,g,tile) sum/sumsq for s
__device__ float g_part_y[B_*NG*16*2];    // per-(b,g,tile) sum/sumsq for y
__device__ float g_sc_s[B_*CC], g_sh_s[B_*CC];   // folded GN scale/shift for s
__device__ float g_sc_y[B_*CC], g_sh_y[B_*CC];   // folded GN scale/shift for y

// ---------------- kernel 1: template path, fully fused ----------------
__global__ void k_template(const float* __restrict__ tf, const float* __restrict__ wt,
                           const float* __restrict__ gw, const float* __restrict__ gb) {
    __shared__ float pre[32*PT];
    __shared__ float s_mean[16], s_rstd[16];
    int b = blockIdx.x >> 1;
    int o0 = (blockIdx.x & 1) * 32;
    int tid = threadIdx.x;

    if (tid < PT) {
        float acc[32];
#pragma unroll
        for (int o = 0; o < 32; o++) acc[o] = 0.f;
        const float* x = tf + (size_t)b*CIN*PT + tid;
        for (int c = 0; c < CIN; c++) {
            float xv = __ldg(x + c*PT);
#pragma unroll
            for (int o = 0; o < 32; o++)
                acc[o] = fmaf(__ldg(wt + (o0+o)*CIN + c), xv, acc[o]);
        }
#pragma unroll
        for (int o = 0; o < 32; o++) pre[o*PT + tid] = acc[o];
    }
    __syncthreads();

    int warp = tid >> 5, lane = tid & 31;
    for (int g = warp; g < 16; g += 8) {
        float s = 0.f, ss = 0.f;
        const float* base = pre + g*2*PT;
        for (int i = lane; i < 2*PT; i += 32) { float v = base[i]; s += v; ss += v*v; }
#pragma unroll
        for (int off = 16; off; off >>= 1) {
            s  += __shfl_down_sync(0xffffffffu, s,  off);
            ss += __shfl_down_sync(0xffffffffu, ss, off);
        }
        if (lane == 0) {
            float m = s / (float)(2*PT);
            float var = ss / (float)(2*PT) - m*m;
            s_mean[g] = m; s_rstd[g] = rsqrtf(var + 1e-5f);
        }
    }
    __syncthreads();

    for (int idx = tid; idx < 32*PT; idx += 256) {
        int c = idx / PT; int g = c >> 1;
        float v = fmaf((pre[idx] - s_mean[g]) * s_rstd[g], gw[o0+c], gb[o0+c]);
        pre[idx] = fmaxf(v, 0.f);
    }
    __syncthreads();

    for (int c = warp; c < 32; c += 8) {
        float s = 0.f;
        for (int i = lane; i < PT; i += 32) s += pre[c*PT + i];
#pragma unroll
        for (int off = 16; off; off >>= 1) s += __shfl_down_sync(0xffffffffu, s, off);
        if (lane == 0) g_tglobal[b*CC + o0 + c] = s * (1.f/(float)PT);
    }
    for (int idx = tid; idx < 32*49; idx += 256) {
        int c = idx / 49, k = idx % 49, kh = k / 7, kw = k % 7;
        const float* p = pre + c*PT + (2*kh)*HT + 2*kw;
        g_tkernel[(b*CC + o0 + c)*49 + k] = 0.25f*(p[0] + p[1] + p[HT] + p[HT+1]);
    }
}

// ---------------- kernel 2: conv1x1 search GEMM, 8x8 register tile ----------------
// grid (16 tiles, 32 b), block 256. Block: 64 out x 256 px, K=256.
__global__ void __launch_bounds__(256) k_search(const float* __restrict__ sf,
                                                const float* __restrict__ ws) {
    __shared__ float As[32][64];     // [kk][o] (transposed for broadcast)
    __shared__ float Bs[32][256];
    int tile = blockIdx.x, b = blockIdx.y;
    int tid = threadIdx.x;
    int tx = tid & 31, ty = tid >> 5;
    float acc[8][8];
#pragma unroll
    for (int i = 0; i < 8; i++)
#pragma unroll
        for (int j = 0; j < 8; j++) acc[i][j] = 0.f;

    for (int k0 = 0; k0 < CIN; k0 += 32) {
        __syncthreads();
        for (int i = tid; i < 512; i += 256) {
            int o = i >> 3, kq = (i & 7) << 2;
            float4 v = *(const float4*)&ws[o*CIN + k0 + kq];
            As[kq+0][o] = v.x; As[kq+1][o] = v.y; As[kq+2][o] = v.z; As[kq+3][o] = v.w;
        }
        for (int i = tid; i < 2048; i += 256) {
            int kk = i >> 6, j = (i & 63) << 2;
            *(float4*)&Bs[kk][j] =
                *(const float4*)&sf[((size_t)b*CIN + k0 + kk)*PS + tile*256 + j];
        }
        __syncthreads();
#pragma unroll
        for (int kk = 0; kk < 32; kk++) {
            float a[8], bv[8];
            *(float4*)&a[0]  = *(const float4*)&As[kk][ty*8];
            *(float4*)&a[4]  = *(const float4*)&As[kk][ty*8 + 4];
            *(float4*)&bv[0] = *(const float4*)&Bs[kk][tx*8];
            *(float4*)&bv[4] = *(const float4*)&Bs[kk][tx*8 + 4];
#pragma unroll
            for (int i = 0; i < 8; i++)
#pragma unroll
                for (int j = 0; j < 8; j++)
                    acc[i][j] = fmaf(a[i], bv[j], acc[i][j]);
        }
    }

    // write + per-group partial stats (warp ty owns groups ty*4 .. ty*4+3)
    float gs[4], gss[4];
#pragma unroll
    for (int q = 0; q < 4; q++) { gs[q] = 0.f; gss[q] = 0.f; }
#pragma unroll
    for (int i = 0; i < 8; i++) {
        int o = ty*8 + i;
        float* dst = &g_s_pre[((size_t)b*CC + o)*PS + tile*256 + tx*8];
        *(float4*)dst       = make_float4(acc[i][0], acc[i][1], acc[i][2], acc[i][3]);
        *(float4*)(dst + 4) = make_float4(acc[i][4], acc[i][5], acc[i][6], acc[i][7]);
        int q = i >> 1;
#pragma unroll
        for (int j = 0; j < 8; j++) { gs[q] += acc[i][j]; gss[q] += acc[i][j]*acc[i][j]; }
    }
#pragma unroll
    for (int q = 0; q < 4; q++) {
#pragma unroll
        for (int off = 16; off; off >>= 1) {
            gs[q]  += __shfl_down_sync(0xffffffffu, gs[q],  off);
            gss[q] += __shfl_down_sync(0xffffffffu, gss[q], off);
        }
    }
    if (tx == 0) {
#pragma unroll
        for (int q = 0; q < 4; q++) {
            int g = ty*4 + q;
            g_part_s[((b*NG + g)*16 + tile)*2 + 0] = gs[q];
            g_part_s[((b*NG + g)*16 + tile)*2 + 1] = gss[q];
        }
    }
}

// ---------------- kernel 3: fold GN stats into per-channel scale/shift ----------------
__global__ void k_stats(int which, int ntiles, float inv_n,
                        const float* __restrict__ gw, const float* __restrict__ gb) {
    int i = blockIdx.x * blockDim.x + threadIdx.x;
    if (i >= B_*CC) return;
    int b = i >> 6, c = i & 63, g = c >> 1;
    const float* part = which ? g_part_y : g_part_s;
    float* sc = which ? g_sc_y : g_sc_s;
    float* sh = which ? g_sh_y : g_sh_s;
    float s = 0.f, ss = 0.f;
    const float* p = part + (size_t)(b*NG + g)*ntiles*2;
    for (int t = 0; t < ntiles; t++) { s += p[2*t]; ss += p[2*t + 1]; }
    float m = s * inv_n;
    float var = ss * inv_n - m*m;
    float r = rsqrtf(var + 1e-5f);
    float scale = r * gw[c];
    sc[i] = scale;
    sh[i] = gb[c] - m*scale;
}

// ---------------- kernel 4: global + local (depthwise 7x7) correlation ----------------
// grid 2048 (b*64+c), block 256. GN-apply + relu fused into the halo load.
// Padded stride 72 so the 8-px inner tile reads are float4.
__global__ void __launch_bounds__(256) k_corr() {
    __shared__ float tile[70*72];
    __shared__ float tk[49];
    int bc = blockIdx.x;
    int tid = threadIdx.x;
    float sc = g_sc_s[bc], sh = g_sh_s[bc], tg = g_tglobal[bc];
    if (tid < 49) tk[tid] = g_tkernel[bc*49 + tid];
    const float* sp = g_s_pre + (size_t)bc*PS;
    for (int idx = tid; idx < 4900; idx += 256) {
        int rr = idx / 70, col = idx - rr*70;
        int r = rr - 3, c = col - 3;
        float v = 0.f;
        if ((unsigned)r < 64u && (unsigned)c < 64u)
            v = fmaxf(fmaf(sp[r*64 + c], sc, sh), 0.f);
        tile[rr*72 + col] = v;
    }
    __syncthreads();
    float* dst = g_corr + (size_t)bc*PS;
#pragma unroll
    for (int it = 0; it < 2; it++) {
        int u = tid + it*256;              // 0..511 units of 8 px
        int y = u >> 3, x8 = (u & 7) << 3;
        float a[8];
#pragma unroll
        for (int j = 0; j < 8; j++) a[j] = 0.f;
#pragma unroll
        for (int kh = 0; kh < 7; kh++) {
            const float* row = tile + (y+kh)*72 + x8;
            float rv[16];
            *(float4*)&rv[0]  = *(const float4*)(row);
            *(float4*)&rv[4]  = *(const float4*)(row + 4);
            *(float4*)&rv[8]  = *(const float4*)(row + 8);
            *(float4*)&rv[12] = *(const float4*)(row + 12);
            if (kh == 3) {
#pragma unroll
                for (int j = 0; j < 8; j++) a[j] = fmaf(tg, rv[j+3], a[j]);
            }
#pragma unroll
            for (int kw = 0; kw < 7; kw++) {
                float w = tk[kh*7 + kw];
#pragma unroll
                for (int j = 0; j < 8; j++) a[j] = fmaf(w, rv[kw + j], a[j]);
            }
        }
        float* d = dst + y*64 + x8;
        *(float4*)d       = make_float4(a[0], a[1], a[2], a[3]);
        *(float4*)(d + 4) = make_float4(a[4], a[5], a[6], a[7]);
    }
}

// ---------------- kernel 5: conv3x3 (implicit GEMM) + GN partials ----------------
// grid (4 px-tiles, 4 oblk, 32 b), block 256.
// Block: 16 out-ch x 32x32 positions. Thread: 8 o x 8 consecutive x.
__global__ void __launch_bounds__(256) k_conv3(const float* __restrict__ wp1) {
    __shared__ float xs[8][34*36];       // 8 in-ch, 34 rows x stride 36
    __shared__ float wsm[16*8*12];       // [o][cc] rows padded to 12
    __shared__ float s_red[8][8];
    int tileI = blockIdx.x, oblk = blockIdx.y, b = blockIdx.z;
    int ty0 = (tileI >> 1) << 5, tx0 = (tileI & 1) << 5;
    int tid = threadIdx.x;
    int og = tid >> 7;                   // 0..1 (8 out-ch each)
    int q128 = tid & 127;
    int py = q128 >> 2, px8 = (q128 & 3) << 3;

    float acc[8][8];
#pragma unroll
    for (int i = 0; i < 8; i++)
#pragma unroll
        for (int j = 0; j < 8; j++) acc[i][j] = 0.f;

    for (int c0 = 0; c0 < CC; c0 += 8) {
        __syncthreads();
        for (int idx = tid; idx < 9248; idx += 256) {
            int cc = idx / 1156, rem = idx - cc*1156;
            int rr = rem / 34, col = rem - rr*34;
            int gy = ty0 + rr - 1, gx = tx0 + col - 1;
            float v = 0.f;
            if ((unsigned)gy < 64u && (unsigned)gx < 64u)
                v = g_corr[((size_t)b*CC + c0 + cc)*PS + gy*64 + gx];
            xs[cc][rr*36 + col] = v;
        }
        for (int idx = tid; idx < 1152; idx += 256) {
            int o = idx / 72, rem = idx - o*72;
            int cc = rem / 9, k = rem - cc*9;
            wsm[(o*8 + cc)*12 + k] = wp1[(((size_t)(oblk*16 + o))*CC + c0 + cc)*9 + k];
        }
        __syncthreads();
#pragma unroll
        for (int cc = 0; cc < 8; cc++) {
            const float* xb = &xs[cc][py*36 + px8];
#pragma unroll
            for (int r = 0; r < 3; r++) {
                float xv[12];
                *(float4*)&xv[0] = *(const float4*)(xb + r*36);
                *(float4*)&xv[4] = *(const float4*)(xb + r*36 + 4);
                *(float4*)&xv[8] = *(const float4*)(xb + r*36 + 8);
#pragma unroll
                for (int o = 0; o < 8; o++) {
                    const float* wp = &wsm[((og*8 + o)*8 + cc)*12 + r*3];
                    float w0 = wp[0], w1 = wp[1], w2 = wp[2];
#pragma unroll
                    for (int j = 0; j < 8; j++)
                        acc[o][j] = fmaf(w0, xv[j],
                                    fmaf(w1, xv[j+1],
                                    fmaf(w2, xv[j+2], acc[o][j])));
                }
            }
        }
    }

#pragma unroll
    for (int o = 0; o < 8; o++) {
        int oo = oblk*16 + og*8 + o;
        float* d = &g_y_pre[((size_t)b*CC + oo)*PS + (ty0+py)*64 + tx0 + px8];
        *(float4*)d       = make_float4(acc[o][0], acc[o][1], acc[o][2], acc[o][3]);
        *(float4*)(d + 4) = make_float4(acc[o][4], acc[o][5], acc[o][6], acc[o][7]);
    }

    // GN partials: thread's 8 o -> 4 local groups (q = o>>1)
    float ps[4] = {0,0,0,0}, pss[4] = {0,0,0,0};
#pragma unroll
    for (int o = 0; o < 8; o++) {
        int q = o >> 1;
#pragma unroll
        for (int j = 0; j < 8; j++) { float v = acc[o][j]; ps[q] += v; pss[q] += v*v; }
    }
#pragma unroll
    for (int q = 0; q < 4; q++)
#pragma unroll
        for (int off = 16; off; off >>= 1) {
            ps[q]  += __shfl_down_sync(0xffffffffu, ps[q],  off);
            pss[q] += __shfl_down_sync(0xffffffffu, pss[q], off);
        }
    int warp = tid >> 5, lane = tid & 31;
    if (lane == 0) {
#pragma unroll
        for (int q = 0; q < 4; q++) {
            s_red[warp][q*2 + 0] = ps[q];
            s_red[warp][q*2 + 1] = pss[q];
        }
    }
    __syncthreads();
    if (tid < 16) {
        int g = tid >> 1, isq = tid & 1;        // local group 0..7
        int ogg = g >> 2, q = g & 3;
        float s = s_red[ogg*4 + 0][q*2 + isq] + s_red[ogg*4 + 1][q*2 + isq]
                + s_red[ogg*4 + 2][q*2 + isq] + s_red[ogg*4 + 3][q*2 + isq];
        g_part_y[((b*NG + oblk*8 + g)*4 + tileI)*2 + isq] = s;
    }
}

// ---------------- kernel 6: GN-apply + relu + final 1x1 + bias ----------------
__global__ void k_out(const float* __restrict__ wp2, const float* __restrict__ bp2,
                      float* __restrict__ out) {
    int i = blockIdx.x*256 + threadIdx.x;     // 0..131071
    int b = i >> 12, p = i & 4095;
    float acc = bp2[0];
    const float* yp = g_y_pre + (size_t)(b*CC)*PS + p;
#pragma unroll 8
    for (int o = 0; o < 64; o++) {
        int bc = b*CC + o;
        float v = fmaxf(fmaf(yp[(size_t)o*PS], g_sc_y[bc], g_sh_y[bc]), 0.f);
        acc = fmaf(wp2[o], v, acc);
    }
    out[i] = acc;
}

// ---------------- launch ----------------
extern "C" void kernel_launch(void* const* d_in, const int* in_sizes, int n_in,
                              void* d_out, int out_size) {
    const float* tf  = (const float*)d_in[0];
    const float* sf  = (const float*)d_in[1];
    const float* wt  = (const float*)d_in[2];
    const float* gtw = (const float*)d_in[3];
    const float* gtb = (const float*)d_in[4];
    const float* ws  = (const float*)d_in[5];
    const float* gsw = (const float*)d_in[6];
    const float* gsb = (const float*)d_in[7];
    const float* wp1 = (const float*)d_in[8];
    const float* gpw = (const float*)d_in[9];
    const float* gpb = (const float*)d_in[10];
    const float* wp2 = (const float*)d_in[11];
    const float* bp2 = (const float*)d_in[12];
    float* out = (float*)d_out;

    k_template<<<64, 256>>>(tf, wt, gtw, gtb);
    k_search<<<dim3(16, 32), 256>>>(sf, ws);
    k_stats<<<8, 256>>>(0, 16, 1.f/8192.f, gsw, gsb);
    k_corr<<<2048, 256>>>();
    k_conv3<<<dim3(4, 4, 32), 256>>>(wp1);
    k_stats<<<8, 256>>>(1, 4, 1.f/8192.f, gpw, gpb);
    k_out<<<512, 256>>>(wp2, bp2, out);
}

// round 5
// speedup vs baseline: 1.0413x; 1.0413x over previous
#include <cuda_runtime.h>

#define B_ 32
#define CIN 256
#define CC 64
#define HS 64
#define PS 4096         // 64*64
#define HT 14
#define PT 196          // 14*14
#define NG 32           // groups (2 channels per group)

typedef unsigned long long ull;

// packed fp32x2 helpers (SASS FFMA2 — only reachable via PTX)
#define FMA2(d, a, b) asm("fma.rn.f32x2 %0, %1, %2, %0;" : "+l"(d) : "l"(a), "l"(b))
__device__ __forceinline__ ull PK(float lo, float hi) {
    ull r; asm("mov.b64 %0, {%1, %2};" : "=l"(r) : "f"(lo), "f"(hi)); return r;
}
__device__ __forceinline__ void UPK(float& lo, float& hi, ull v) {
    asm("mov.b64 {%0, %1}, %2;" : "=f"(lo), "=f"(hi) : "l"(v));
}

// ---------------- device scratch (no allocations allowed) ----------------
__device__ float g_s_pre[B_*CC*PS];       // conv1x1(search) pre-GN
__device__ float g_corr[B_*CC*PS];        // global + local correlation
__device__ float g_y_pre[B_*CC*PS];       // conv3x3 pre-GN
__device__ float g_tglobal[B_*CC];        // mean of relu(gn(t)) per (b,c)
__device__ float g_tkernel[B_*CC*49];     // 7x7 pooled template kernel
__device__ float g_part_s[B_*NG*32*2];    // per-(b,g,tile) sum/sumsq for s
__device__ float g_part_y[B_*NG*16*2];    // per-(b,g,tile) sum/sumsq for y
__device__ float g_sc_s[B_*CC], g_sh_s[B_*CC];   // folded GN scale/shift for s
__device__ float g_sc_y[B_*CC], g_sh_y[B_*CC];   // folded GN scale/shift for y

// ---------------- kernel 1: template path, fully fused ----------------
__global__ void k_template(const float* __restrict__ tf, const float* __restrict__ wt,
                           const float* __restrict__ gw, const float* __restrict__ gb) {
    __shared__ float pre[32*PT];
    __shared__ float s_mean[16], s_rstd[16];
    int b = blockIdx.x >> 1;
    int o0 = (blockIdx.x & 1) * 32;
    int tid = threadIdx.x;

    if (tid < PT) {
        float acc[32];
#pragma unroll
        for (int o = 0; o < 32; o++) acc[o] = 0.f;
        const float* x = tf + (size_t)b*CIN*PT + tid;
        for (int c = 0; c < CIN; c++) {
            float xv = __ldg(x + c*PT);
#pragma unroll
            for (int o = 0; o < 32; o++)
                acc[o] = fmaf(__ldg(wt + (o0+o)*CIN + c), xv, acc[o]);
        }
#pragma unroll
        for (int o = 0; o < 32; o++) pre[o*PT + tid] = acc[o];
    }
    __syncthreads();

    int warp = tid >> 5, lane = tid & 31;
    for (int g = warp; g < 16; g += 8) {
        float s = 0.f, ss = 0.f;
        const float* base = pre + g*2*PT;
        for (int i = lane; i < 2*PT; i += 32) { float v = base[i]; s += v; ss += v*v; }
#pragma unroll
        for (int off = 16; off; off >>= 1) {
            s  += __shfl_down_sync(0xffffffffu, s,  off);
            ss += __shfl_down_sync(0xffffffffu, ss, off);
        }
        if (lane == 0) {
            float m = s / (float)(2*PT);
            float var = ss / (float)(2*PT) - m*m;
            s_mean[g] = m; s_rstd[g] = rsqrtf(var + 1e-5f);
        }
    }
    __syncthreads();

    for (int idx = tid; idx < 32*PT; idx += 256) {
        int c = idx / PT; int g = c >> 1;
        float v = fmaf((pre[idx] - s_mean[g]) * s_rstd[g], gw[o0+c], gb[o0+c]);
        pre[idx] = fmaxf(v, 0.f);
    }
    __syncthreads();

    for (int c = warp; c < 32; c += 8) {
        float s = 0.f;
        for (int i = lane; i < PT; i += 32) s += pre[c*PT + i];
#pragma unroll
        for (int off = 16; off; off >>= 1) s += __shfl_down_sync(0xffffffffu, s, off);
        if (lane == 0) g_tglobal[b*CC + o0 + c] = s * (1.f/(float)PT);
    }
    for (int idx = tid; idx < 32*49; idx += 256) {
        int c = idx / 49, k = idx % 49, kh = k / 7, kw = k % 7;
        const float* p = pre + c*PT + (2*kh)*HT + 2*kw;
        g_tkernel[(b*CC + o0 + c)*49 + k] = 0.25f*(p[0] + p[1] + p[HT] + p[HT+1]);
    }
}

// ---------------- kernel 2: conv1x1 search GEMM, FFMA2 ----------------
// grid (32 tiles, 32 b), block 256. Block: 64 out x 128 px, K=256.
// Thread: 8 o x 4 px (2 packed pairs per o).
__global__ void __launch_bounds__(256) k_search(const float* __restrict__ sf,
                                                const float* __restrict__ ws) {
    __shared__ float As2[32][128];   // [kk][o*2 + dup] duplicated pairs
    __shared__ float Bs[32][128];
    int tile = blockIdx.x, b = blockIdx.y;
    int tid = threadIdx.x;
    int tx = tid & 31, ty = tid >> 5;
    ull acc[8][2];
#pragma unroll
    for (int i = 0; i < 8; i++) { acc[i][0] = 0ULL; acc[i][1] = 0ULL; }

    for (int k0 = 0; k0 < CIN; k0 += 32) {
        __syncthreads();
        for (int i = tid; i < 512; i += 256) {
            int o = i >> 3, kq = (i & 7) << 2;
            float4 v = *(const float4*)&ws[o*CIN + k0 + kq];
            As2[kq+0][o*2] = v.x; As2[kq+0][o*2+1] = v.x;
            As2[kq+1][o*2] = v.y; As2[kq+1][o*2+1] = v.y;
            As2[kq+2][o*2] = v.z; As2[kq+2][o*2+1] = v.z;
            As2[kq+3][o*2] = v.w; As2[kq+3][o*2+1] = v.w;
        }
        for (int i = tid; i < 1024; i += 256) {
            int kk = i >> 5, j = (i & 31) << 2;
            *(float4*)&Bs[kk][j] =
                *(const float4*)&sf[((size_t)b*CIN + k0 + kk)*PS + tile*128 + j];
        }
        __syncthreads();
#pragma unroll
        for (int kk = 0; kk < 32; kk++) {
            float4 bv = *(const float4*)&Bs[kk][tx*4];
            ull b0 = PK(bv.x, bv.y), b1 = PK(bv.z, bv.w);
#pragma unroll
            for (int i = 0; i < 8; i++) {
                ull a = *(const ull*)&As2[kk][(ty*8 + i)*2];
                FMA2(acc[i][0], a, b0);
                FMA2(acc[i][1], a, b1);
            }
        }
    }

    // write + per-group partial stats (warp ty owns groups ty*4 .. ty*4+3)
    float gs[4], gss[4];
#pragma unroll
    for (int q = 0; q < 4; q++) { gs[q] = 0.f; gss[q] = 0.f; }
#pragma unroll
    for (int i = 0; i < 8; i++) {
        int o = ty*8 + i;
        float f0, f1, f2, f3;
        UPK(f0, f1, acc[i][0]);
        UPK(f2, f3, acc[i][1]);
        *(float4*)&g_s_pre[((size_t)b*CC + o)*PS + tile*128 + tx*4] =
            make_float4(f0, f1, f2, f3);
        int q = i >> 1;
        gs[q]  += f0 + f1 + f2 + f3;
        gss[q] += f0*f0 + f1*f1 + f2*f2 + f3*f3;
    }
#pragma unroll
    for (int q = 0; q < 4; q++) {
#pragma unroll
        for (int off = 16; off; off >>= 1) {
            gs[q]  += __shfl_down_sync(0xffffffffu, gs[q],  off);
            gss[q] += __shfl_down_sync(0xffffffffu, gss[q], off);
        }
    }
    if (tx == 0) {
#pragma unroll
        for (int q = 0; q < 4; q++) {
            int g = ty*4 + q;
            g_part_s[((b*NG + g)*32 + tile)*2 + 0] = gs[q];
            g_part_s[((b*NG + g)*32 + tile)*2 + 1] = gss[q];
        }
    }
}

// ---------------- kernel 3: fold GN stats into per-channel scale/shift ----------------
__global__ void k_stats(int which, int ntiles, float inv_n,
                        const float* __restrict__ gw, const float* __restrict__ gb) {
    int i = blockIdx.x * blockDim.x + threadIdx.x;
    if (i >= B_*CC) return;
    int b = i >> 6, c = i & 63, g = c >> 1;
    const float* part = which ? g_part_y : g_part_s;
    float* sc = which ? g_sc_y : g_sc_s;
    float* sh = which ? g_sh_y : g_sh_s;
    float s = 0.f, ss = 0.f;
    const float* p = part + (size_t)(b*NG + g)*ntiles*2;
    for (int t = 0; t < ntiles; t++) { s += p[2*t]; ss += p[2*t + 1]; }
    float m = s * inv_n;
    float var = ss * inv_n - m*m;
    float r = rsqrtf(var + 1e-5f);
    float scale = r * gw[c];
    sc[i] = scale;
    sh[i] = gb[c] - m*scale;
}

// ---------------- kernel 4: global + local (depthwise 7x7) correlation ----------------
__global__ void __launch_bounds__(256) k_corr() {
    __shared__ float tile[70*72];
    __shared__ float tk[49];
    int bc = blockIdx.x;
    int tid = threadIdx.x;
    float sc = g_sc_s[bc], sh = g_sh_s[bc], tg = g_tglobal[bc];
    if (tid < 49) tk[tid] = g_tkernel[bc*49 + tid];
    const float* sp = g_s_pre + (size_t)bc*PS;
    for (int idx = tid; idx < 4900; idx += 256) {
        int rr = idx / 70, col = idx - rr*70;
        int r = rr - 3, c = col - 3;
        float v = 0.f;
        if ((unsigned)r < 64u && (unsigned)c < 64u)
            v = fmaxf(fmaf(sp[r*64 + c], sc, sh), 0.f);
        tile[rr*72 + col] = v;
    }
    __syncthreads();
    float* dst = g_corr + (size_t)bc*PS;
#pragma unroll
    for (int it = 0; it < 2; it++) {
        int u = tid + it*256;              // 0..511 units of 8 px
        int y = u >> 3, x8 = (u & 7) << 3;
        float a[8];
#pragma unroll
        for (int j = 0; j < 8; j++) a[j] = 0.f;
#pragma unroll
        for (int kh = 0; kh < 7; kh++) {
            const float* row = tile + (y+kh)*72 + x8;
            float rv[16];
            *(float4*)&rv[0]  = *(const float4*)(row);
            *(float4*)&rv[4]  = *(const float4*)(row + 4);
            *(float4*)&rv[8]  = *(const float4*)(row + 8);
            *(float4*)&rv[12] = *(const float4*)(row + 12);
            if (kh == 3) {
#pragma unroll
                for (int j = 0; j < 8; j++) a[j] = fmaf(tg, rv[j+3], a[j]);
            }
#pragma unroll
            for (int kw = 0; kw < 7; kw++) {
                float w = tk[kh*7 + kw];
#pragma unroll
                for (int j = 0; j < 8; j++) a[j] = fmaf(w, rv[kw + j], a[j]);
            }
        }
        float* d = dst + y*64 + x8;
        *(float4*)d       = make_float4(a[0], a[1], a[2], a[3]);
        *(float4*)(d + 4) = make_float4(a[4], a[5], a[6], a[7]);
    }
}

// ---------------- kernel 5: conv3x3 (implicit GEMM, FFMA2) + GN partials ----------------
// grid (8 px-tiles [4 row x 2 col], 4 oblk, 32 b), block 256.
// Block: 16 out-ch x (16 rows x 32 cols). Thread: 4 o x 8 px (4 packed pairs).
__global__ void __launch_bounds__(256) k_conv3(const float* __restrict__ wp1) {
    __shared__ float xs[8][18*34];       // 8 in-ch, 18 rows x 34 cols (stride 34)
    __shared__ float wsm2[16*8*9*2];     // duplicated weight pairs
    __shared__ float s_red[8][8];
    int tileI = blockIdx.x, oblk = blockIdx.y, b = blockIdx.z;
    int ty0 = (tileI >> 1) << 4, tx0 = (tileI & 1) << 5;
    int tid = threadIdx.x;
    int og = tid >> 6;                   // 0..3 (4 out-ch each)
    int unit = tid & 63;
    int py = unit >> 2, px8 = (unit & 3) << 3;

    ull acc[4][4];
#pragma unroll
    for (int i = 0; i < 4; i++)
#pragma unroll
        for (int j = 0; j < 4; j++) acc[i][j] = 0ULL;

    for (int c0 = 0; c0 < CC; c0 += 8) {
        __syncthreads();
        for (int idx = tid; idx < 4896; idx += 256) {
            int cc = idx / 612, rem = idx - cc*612;
            int rr = rem / 34, col = rem - rr*34;
            int gy = ty0 + rr - 1, gx = tx0 + col - 1;
            float v = 0.f;
            if ((unsigned)gy < 64u && (unsigned)gx < 64u)
                v = g_corr[((size_t)b*CC + c0 + cc)*PS + gy*64 + gx];
            xs[cc][rem] = v;
        }
        for (int idx = tid; idx < 1152; idx += 256) {
            int o = idx / 72, rem = idx - o*72;      // rem = cc*9 + k
            float w = wp1[(((size_t)(oblk*16 + o))*CC + c0)*9 + rem];
            wsm2[(o*72 + rem)*2 + 0] = w;
            wsm2[(o*72 + rem)*2 + 1] = w;
        }
        __syncthreads();
#pragma unroll
        for (int cc = 0; cc < 8; cc++) {
#pragma unroll
            for (int r = 0; r < 3; r++) {
                const float* xb = &xs[cc][(py+r)*34 + px8];
                float2 q0 = *(const float2*)(xb);
                float2 q1 = *(const float2*)(xb + 2);
                float2 q2 = *(const float2*)(xb + 4);
                float2 q3 = *(const float2*)(xb + 6);
                float2 q4 = *(const float2*)(xb + 8);
                ull ev0 = PK(q0.x, q0.y), ev1 = PK(q1.x, q1.y);
                ull ev2 = PK(q2.x, q2.y), ev3 = PK(q3.x, q3.y);
                ull ev4 = PK(q4.x, q4.y);
                ull od0 = PK(q0.y, q1.x), od1 = PK(q1.y, q2.x);
                ull od2 = PK(q2.y, q3.x), od3 = PK(q3.y, q4.x);
#pragma unroll
                for (int o = 0; o < 4; o++) {
                    const float* wb = &wsm2[(((og*4 + o)*8 + cc)*9 + r*3)*2];
                    ull w0 = *(const ull*)(wb);
                    ull w1 = *(const ull*)(wb + 2);
                    ull w2 = *(const ull*)(wb + 4);
                    FMA2(acc[o][0], w0, ev0); FMA2(acc[o][0], w1, od0); FMA2(acc[o][0], w2, ev1);
                    FMA2(acc[o][1], w0, ev1); FMA2(acc[o][1], w1, od1); FMA2(acc[o][1], w2, ev2);
                    FMA2(acc[o][2], w0, ev2); FMA2(acc[o][2], w1, od2); FMA2(acc[o][2], w2, ev3);
                    FMA2(acc[o][3], w0, ev3); FMA2(acc[o][3], w1, od3); FMA2(acc[o][3], w2, ev4);
                }
            }
        }
    }

    // store + GN partials (thread's 4 o -> 2 local groups)
    float ps[2] = {0.f, 0.f}, pss[2] = {0.f, 0.f};
#pragma unroll
    for (int o = 0; o < 4; o++) {
        float f[8];
        UPK(f[0], f[1], acc[o][0]);
        UPK(f[2], f[3], acc[o][1]);
        UPK(f[4], f[5], acc[o][2]);
        UPK(f[6], f[7], acc[o][3]);
        int oo = oblk*16 + og*4 + o;
        float* d = &g_y_pre[((size_t)b*CC + oo)*PS + (ty0+py)*64 + tx0 + px8];
        *(float4*)d       = make_float4(f[0], f[1], f[2], f[3]);
        *(float4*)(d + 4) = make_float4(f[4], f[5], f[6], f[7]);
        int q = o >> 1;
#pragma unroll
        for (int j = 0; j < 8; j++) { ps[q] += f[j]; pss[q] += f[j]*f[j]; }
    }
#pragma unroll
    for (int q = 0; q < 2; q++)
#pragma unroll
        for (int off = 16; off; off >>= 1) {
            ps[q]  += __shfl_down_sync(0xffffffffu, ps[q],  off);
            pss[q] += __shfl_down_sync(0xffffffffu, pss[q], off);
        }
    int warp = tid >> 5, lane = tid & 31;
    if (lane == 0) {
        s_red[warp][0] = ps[0];  s_red[warp][1] = pss[0];
        s_red[warp][2] = ps[1];  s_red[warp][3] = pss[1];
    }
    __syncthreads();
    if (tid < 16) {
        int g = tid >> 1, isq = tid & 1;      // local group 0..7
        int ogq = g >> 1, gi = g & 1;
        float s = s_red[ogq*2][gi*2 + isq] + s_red[ogq*2 + 1][gi*2 + isq];
        g_part_y[((b*NG + oblk*8 + g)*8 + tileI)*2 + isq] = s;
    }
}

// ---------------- kernel 6: GN-apply + relu + final 1x1 + bias ----------------
__global__ void k_out(const float* __restrict__ wp2, const float* __restrict__ bp2,
                      float* __restrict__ out) {
    int i = blockIdx.x*256 + threadIdx.x;     // 0..131071
    int b = i >> 12, p = i & 4095;
    float acc = bp2[0];
    const float* yp = g_y_pre + (size_t)(b*CC)*PS + p;
#pragma unroll 8
    for (int o = 0; o < 64; o++) {
        int bc = b*CC + o;
        float v = fmaxf(fmaf(yp[(size_t)o*PS], g_sc_y[bc], g_sh_y[bc]), 0.f);
        acc = fmaf(wp2[o], v, acc);
    }
    out[i] = acc;
}

// ---------------- launch ----------------
extern "C" void kernel_launch(void* const* d_in, const int* in_sizes, int n_in,
                              void* d_out, int out_size) {
    const float* tf  = (const float*)d_in[0];
    const float* sf  = (const float*)d_in[1];
    const float* wt  = (const float*)d_in[2];
    const float* gtw = (const float*)d_in[3];
    const float* gtb = (const float*)d_in[4];
    const float* ws  = (const float*)d_in[5];
    const float* gsw = (const float*)d_in[6];
    const float* gsb = (const float*)d_in[7];
    const float* wp1 = (const float*)d_in[8];
    const float* gpw = (const float*)d_in[9];
    const float* gpb = (const float*)d_in[10];
    const float* wp2 = (const float*)d_in[11];
    const float* bp2 = (const float*)d_in[12];
    float* out = (float*)d_out;

    k_template<<<64, 256>>>(tf, wt, gtw, gtb);
    k_search<<<dim3(32, 32), 256>>>(sf, ws);
    k_stats<<<8, 256>>>(0, 32, 1.f/8192.f, gsw, gsb);
    k_corr<<<2048, 256>>>();
    k_conv3<<<dim3(8, 4, 32), 256>>>(wp1);
    k_stats<<<8, 256>>>(1, 8, 1.f/8192.f, gpw, gpb);
    k_out<<<512, 256>>>(wp2, bp2, out);
}

// round 6
// speedup vs baseline: 1.6955x; 1.6283x over previous
#include <cuda_runtime.h>
#include <cstdint>

#define B_ 32
#define CIN 256
#define CC 64
#define HS 64
#define PS 4096         // 64*64
#define HT 14
#define PT 196          // 14*14
#define NG 32           // groups (2 channels per group)

typedef unsigned long long ull;

// packed fp32x2 helpers (SASS FFMA2 — only reachable via PTX)
#define FMA2(d, a, b) asm("fma.rn.f32x2 %0, %1, %2, %0;" : "+l"(d) : "l"(a), "l"(b))
__device__ __forceinline__ ull PK(float lo, float hi) {
    ull r; asm("mov.b64 %0, {%1, %2};" : "=l"(r) : "f"(lo), "f"(hi)); return r;
}
__device__ __forceinline__ void UPK(float& lo, float& hi, ull v) {
    asm("mov.b64 {%0, %1}, %2;" : "=f"(lo), "=f"(hi) : "l"(v));
}

// cp.async helpers
__device__ __forceinline__ uint32_t sm32(const void* p) {
    return (uint32_t)__cvta_generic_to_shared(p);
}
__device__ __forceinline__ void cp16(uint32_t dst, const void* src) {
    asm volatile("cp.async.ca.shared.global [%0], [%1], 16;\n" :: "r"(dst), "l"(src));
}
#define CP_COMMIT asm volatile("cp.async.commit_group;\n")
#define CP_WAIT0  asm volatile("cp.async.wait_group 0;\n")
#define CP_WAIT1  asm volatile("cp.async.wait_group 1;\n")

// ---------------- device scratch (no allocations allowed) ----------------
__device__ float g_s_pre[B_*CC*PS];       // conv1x1(search) pre-GN
__device__ float g_corr[B_*CC*PS];        // global + local correlation
__device__ float g_y_pre[B_*CC*PS];       // conv3x3 pre-GN
__device__ float g_tglobal[B_*CC];        // mean of relu(gn(t)) per (b,c)
__device__ float g_tkernel[B_*CC*49];     // 7x7 pooled template kernel
__device__ float g_part_s[B_*NG*32*2];    // per-(b,g,tile) sum/sumsq for s
__device__ float g_part_y[B_*NG*8*2];     // per-(b,g,tile) sum/sumsq for y

// ---------------- kernel 1: template path (smem weights + FFMA2) ----------------
// grid 128 (= b*4 + quarter), block 256. Each block: 16 output channels (8 groups).
__global__ void __launch_bounds__(256) k_template(
        const float* __restrict__ tf, const float* __restrict__ wt,
        const float* __restrict__ gw, const float* __restrict__ gb) {
    __shared__ __align__(8) float wsm[256*18];   // [c][o], stride 18 (8B-aligned pairs)
    __shared__ float pre[16*PT];
    __shared__ float s_mean[8], s_rstd[8];
    int b = blockIdx.x >> 2;
    int o0 = (blockIdx.x & 3) * 16;
    int tid = threadIdx.x;

    for (int idx = tid; idx < 4096; idx += 256) {
        int c = idx & 255, o = idx >> 8;
        wsm[c*18 + o] = wt[(o0+o)*CIN + c];
    }
    __syncthreads();

    if (tid < PT) {
        ull acc[8];
#pragma unroll
        for (int i = 0; i < 8; i++) acc[i] = 0ULL;
        const float* x = tf + (size_t)b*CIN*PT + tid;
#pragma unroll 4
        for (int c = 0; c < CIN; c++) {
            float xv = __ldg(x + c*PT);
            ull xd = PK(xv, xv);
#pragma unroll
            for (int i = 0; i < 8; i++) {
                ull w = *(const ull*)&wsm[c*18 + 2*i];
                FMA2(acc[i], w, xd);
            }
        }
#pragma unroll
        for (int i = 0; i < 8; i++) {
            float f0, f1; UPK(f0, f1, acc[i]);
            pre[(2*i)*PT + tid]   = f0;
            pre[(2*i+1)*PT + tid] = f1;
        }
    }
    __syncthreads();

    int warp = tid >> 5, lane = tid & 31;
    {   // 8 groups, one per warp
        int g = warp;
        float s = 0.f, ss = 0.f;
        const float* base = pre + g*2*PT;
        for (int i = lane; i < 2*PT; i += 32) { float v = base[i]; s += v; ss += v*v; }
#pragma unroll
        for (int off = 16; off; off >>= 1) {
            s  += __shfl_down_sync(0xffffffffu, s,  off);
            ss += __shfl_down_sync(0xffffffffu, ss, off);
        }
        if (lane == 0) {
            float m = s / (float)(2*PT);
            float var = ss / (float)(2*PT) - m*m;
            s_mean[g] = m; s_rstd[g] = rsqrtf(var + 1e-5f);
        }
    }
    __syncthreads();

    for (int idx = tid; idx < 16*PT; idx += 256) {
        int c = idx / PT; int g = c >> 1;
        float v = fmaf((pre[idx] - s_mean[g]) * s_rstd[g], gw[o0+c], gb[o0+c]);
        pre[idx] = fmaxf(v, 0.f);
    }
    __syncthreads();

    for (int c = warp; c < 16; c += 8) {
        float s = 0.f;
        for (int i = lane; i < PT; i += 32) s += pre[c*PT + i];
#pragma unroll
        for (int off = 16; off; off >>= 1) s += __shfl_down_sync(0xffffffffu, s, off);
        if (lane == 0) g_tglobal[b*CC + o0 + c] = s * (1.f/(float)PT);
    }
    for (int idx = tid; idx < 16*49; idx += 256) {
        int c = idx / 49, k = idx % 49, kh = k / 7, kw = k % 7;
        const float* p = pre + c*PT + (2*kh)*HT + 2*kw;
        g_tkernel[(b*CC + o0 + c)*49 + k] = 0.25f*(p[0] + p[1] + p[HT] + p[HT+1]);
    }
}

// ---------------- kernel 2: conv1x1 search GEMM, cp.async double-buffered ----------------
// grid (32 tiles, 32 b), block 256. Block: 64 out x 128 px, K=256.
__global__ void __launch_bounds__(256) k_search(const float* __restrict__ sf,
                                                const float* __restrict__ ws) {
    __shared__ __align__(16) float As[2][2048];   // [o*32 + kk]
    __shared__ __align__(16) float Bs[2][4096];   // [kk*128 + j]
    int tile = blockIdx.x, b = blockIdx.y;
    int tid = threadIdx.x;
    int tx = tid & 31, ty = tid >> 5;

    // stage issue: k0 = s*32, into buf
    auto issue = [&](int s, int buf) {
        int k0 = s * 32;
#pragma unroll
        for (int i = 0; i < 4; i++) {
            int t = tid*4 + i;                 // 0..1023
            int kk = t >> 5, j4 = (t & 31) << 2;
            cp16(sm32(&Bs[buf][kk*128 + j4]),
                 sf + ((size_t)b*CIN + k0 + kk)*PS + tile*128 + j4);
        }
#pragma unroll
        for (int i = 0; i < 2; i++) {
            int slot = tid*2 + i;              // 0..511
            int o = slot >> 3, c4 = (slot & 7) << 2;
            cp16(sm32(&As[buf][o*32 + c4]), ws + o*CIN + k0 + c4);
        }
        CP_COMMIT;
    };

    ull acc[8][2];
#pragma unroll
    for (int i = 0; i < 8; i++) { acc[i][0] = 0ULL; acc[i][1] = 0ULL; }

    issue(0, 0);
    for (int s = 0; s < 8; s++) {
        int cur = s & 1;
        if (s < 7) { issue(s+1, 1-cur); CP_WAIT1; }
        else       { CP_WAIT0; }
        __syncthreads();
#pragma unroll
        for (int kk = 0; kk < 32; kk++) {
            float4 bv = *(const float4*)&Bs[cur][kk*128 + tx*4];
            ull b0 = PK(bv.x, bv.y), b1 = PK(bv.z, bv.w);
#pragma unroll
            for (int i = 0; i < 8; i++) {
                float w = As[cur][(ty*8 + i)*32 + kk];
                ull a = PK(w, w);
                FMA2(acc[i][0], a, b0);
                FMA2(acc[i][1], a, b1);
            }
        }
        __syncthreads();
    }

    // write + per-group partial stats (warp ty owns groups ty*4 .. ty*4+3)
    float gs[4], gss[4];
#pragma unroll
    for (int q = 0; q < 4; q++) { gs[q] = 0.f; gss[q] = 0.f; }
#pragma unroll
    for (int i = 0; i < 8; i++) {
        int o = ty*8 + i;
        float f0, f1, f2, f3;
        UPK(f0, f1, acc[i][0]);
        UPK(f2, f3, acc[i][1]);
        *(float4*)&g_s_pre[((size_t)b*CC + o)*PS + tile*128 + tx*4] =
            make_float4(f0, f1, f2, f3);
        int q = i >> 1;
        gs[q]  += f0 + f1 + f2 + f3;
        gss[q] += f0*f0 + f1*f1 + f2*f2 + f3*f3;
    }
#pragma unroll
    for (int q = 0; q < 4; q++) {
#pragma unroll
        for (int off = 16; off; off >>= 1) {
            gs[q]  += __shfl_down_sync(0xffffffffu, gs[q],  off);
            gss[q] += __shfl_down_sync(0xffffffffu, gss[q], off);
        }
    }
    if (tx == 0) {
#pragma unroll
        for (int q = 0; q < 4; q++) {
            int g = ty*4 + q;
            g_part_s[((b*NG + g)*32 + tile)*2 + 0] = gs[q];
            g_part_s[((b*NG + g)*32 + tile)*2 + 1] = gss[q];
        }
    }
}

// ---------------- kernel 3: global + local (depthwise 7x7) correlation ----------------
// GN stats folded in per block (reads its group's 32 partials).
__global__ void __launch_bounds__(256) k_corr(const float* __restrict__ gsw,
                                              const float* __restrict__ gsb) {
    __shared__ float tile[70*72];
    __shared__ float tk[49];
    __shared__ float s_scsh[2];
    int bc = blockIdx.x;
    int b = bc >> 6, c = bc & 63, g = c >> 1;
    int tid = threadIdx.x;
    if (tid < 32) {
        float s  = g_part_s[((b*NG + g)*32 + tid)*2 + 0];
        float ss = g_part_s[((b*NG + g)*32 + tid)*2 + 1];
#pragma unroll
        for (int off = 16; off; off >>= 1) {
            s  += __shfl_down_sync(0xffffffffu, s,  off);
            ss += __shfl_down_sync(0xffffffffu, ss, off);
        }
        if (tid == 0) {
            float m = s * (1.f/8192.f);
            float var = ss * (1.f/8192.f) - m*m;
            float r = rsqrtf(var + 1e-5f);
            float scale = r * gsw[c];
            s_scsh[0] = scale;
            s_scsh[1] = gsb[c] - m*scale;
        }
    }
    if (tid < 49) tk[tid] = g_tkernel[bc*49 + tid];
    __syncthreads();
    float sc = s_scsh[0], sh = s_scsh[1], tg = g_tglobal[bc];

    const float* sp = g_s_pre + (size_t)bc*PS;
    for (int idx = tid; idx < 4900; idx += 256) {
        int rr = idx / 70, col = idx - rr*70;
        int r = rr - 3, cx = col - 3;
        float v = 0.f;
        if ((unsigned)r < 64u && (unsigned)cx < 64u)
            v = fmaxf(fmaf(sp[r*64 + cx], sc, sh), 0.f);
        tile[rr*72 + col] = v;
    }
    __syncthreads();
    float* dst = g_corr + (size_t)bc*PS;
#pragma unroll
    for (int it = 0; it < 2; it++) {
        int u = tid + it*256;              // 0..511 units of 8 px
        int y = u >> 3, x8 = (u & 7) << 3;
        float a[8];
#pragma unroll
        for (int j = 0; j < 8; j++) a[j] = 0.f;
#pragma unroll
        for (int kh = 0; kh < 7; kh++) {
            const float* row = tile + (y+kh)*72 + x8;
            float rv[16];
            *(float4*)&rv[0]  = *(const float4*)(row);
            *(float4*)&rv[4]  = *(const float4*)(row + 4);
            *(float4*)&rv[8]  = *(const float4*)(row + 8);
            *(float4*)&rv[12] = *(const float4*)(row + 12);
            if (kh == 3) {
#pragma unroll
                for (int j = 0; j < 8; j++) a[j] = fmaf(tg, rv[j+3], a[j]);
            }
#pragma unroll
            for (int kw = 0; kw < 7; kw++) {
                float w = tk[kh*7 + kw];
#pragma unroll
                for (int j = 0; j < 8; j++) a[j] = fmaf(w, rv[kw + j], a[j]);
            }
        }
        float* d = dst + y*64 + x8;
        *(float4*)d       = make_float4(a[0], a[1], a[2], a[3]);
        *(float4*)(d + 4) = make_float4(a[4], a[5], a[6], a[7]);
    }
}

// ---------------- kernel 4: conv3x3 (FFMA2, pipelined) + GN partials ----------------
// grid (8 px-tiles [4 row x 2 col], 4 oblk, 32 b), block 256.
// Block: 16 out-ch x (16 rows x 32 cols). Thread: 4 o x 8 px.
// Weights for the whole block preloaded once via cp.async; x tiles
// double-buffered via register staging (LDG overlaps compute).
__global__ void __launch_bounds__(256, 2) k_conv3(const float* __restrict__ wp1) {
    __shared__ __align__(16) float wsm[9216];     // [(o*64+c)*9 + k] — matches gmem layout
    __shared__ __align__(16) float xs[2][4896];   // [cc*612 + rr*34 + col]
    __shared__ float s_red[8][8];
    int tileI = blockIdx.x, oblk = blockIdx.y, b = blockIdx.z;
    int ty0 = (tileI >> 1) << 4, tx0 = (tileI & 1) << 5;
    int tid = threadIdx.x;
    int og = tid >> 6;                   // 0..3 (4 out-ch each)
    int unit = tid & 63;
    int py = unit >> 2, px8 = (unit & 3) << 3;

    // full weight preload (contiguous 9216 floats)
    {
        const float* wg = wp1 + (size_t)(oblk*16)*CC*9;
#pragma unroll
        for (int i = 0; i < 9; i++) {
            int chunk = tid + i*256;     // 0..2303
            cp16(sm32(&wsm[chunk*4]), wg + chunk*4);
        }
        CP_COMMIT;
    }

    float st[20];
    auto prefetch = [&](int s) {
        int c0 = s * 8;
#pragma unroll
        for (int i = 0; i < 20; i++) {
            int e = tid + i*256;
            float v = 0.f;
            if (e < 4896) {
                int cc = e / 612, rem = e - cc*612;
                int rr = rem / 34, col = rem - rr*34;
                int gy = ty0 + rr - 1, gx = tx0 + col - 1;
                if ((unsigned)gy < 64u && (unsigned)gx < 64u)
                    v = g_corr[((size_t)b*CC + c0 + cc)*PS + gy*64 + gx];
            }
            st[i] = v;
        }
    };
    auto stsStage = [&](int buf) {
#pragma unroll
        for (int i = 0; i < 20; i++) {
            int e = tid + i*256;
            if (e < 4896) xs[buf][e] = st[i];
        }
    };

    prefetch(0);
    stsStage(0);
    CP_WAIT0;                 // weights in
    __syncthreads();
    prefetch(1);

    ull acc[4][4];
#pragma unroll
    for (int i = 0; i < 4; i++)
#pragma unroll
        for (int j = 0; j < 4; j++) acc[i][j] = 0ULL;

    for (int s = 0; s < 8; s++) {
        int cb = s & 1, c0 = s * 8;
#pragma unroll
        for (int cc = 0; cc < 8; cc++) {
#pragma unroll
            for (int r = 0; r < 3; r++) {
                const float* xb = &xs[cb][cc*612 + (py+r)*34 + px8];
                float2 q0 = *(const float2*)(xb);
                float2 q1 = *(const float2*)(xb + 2);
                float2 q2 = *(const float2*)(xb + 4);
                float2 q3 = *(const float2*)(xb + 6);
                float2 q4 = *(const float2*)(xb + 8);
                ull ev0 = PK(q0.x, q0.y), ev1 = PK(q1.x, q1.y);
                ull ev2 = PK(q2.x, q2.y), ev3 = PK(q3.x, q3.y);
                ull ev4 = PK(q4.x, q4.y);
                ull od0 = PK(q0.y, q1.x), od1 = PK(q1.y, q2.x);
                ull od2 = PK(q2.y, q3.x), od3 = PK(q3.y, q4.x);
#pragma unroll
                for (int o = 0; o < 4; o++) {
                    const float* wb = &wsm[((og*4 + o)*64 + c0 + cc)*9 + r*3];
                    float w0f = wb[0], w1f = wb[1], w2f = wb[2];
                    ull w0 = PK(w0f, w0f), w1 = PK(w1f, w1f), w2 = PK(w2f, w2f);
                    FMA2(acc[o][0], w0, ev0); FMA2(acc[o][0], w1, od0); FMA2(acc[o][0], w2, ev1);
                    FMA2(acc[o][1], w0, ev1); FMA2(acc[o][1], w1, od1); FMA2(acc[o][1], w2, ev2);
                    FMA2(acc[o][2], w0, ev2); FMA2(acc[o][2], w1, od2); FMA2(acc[o][2], w2, ev3);
                    FMA2(acc[o][3], w0, ev3); FMA2(acc[o][3], w1, od3); FMA2(acc[o][3], w2, ev4);
                }
            }
        }
        if (s < 7) stsStage(1 - cb);
        __syncthreads();
        if (s < 6) prefetch(s + 2);
    }

    // store + GN partials (thread's 4 o -> 2 local groups)
    float ps[2] = {0.f, 0.f}, pss[2] = {0.f, 0.f};
#pragma unroll
    for (int o = 0; o < 4; o++) {
        float f[8];
        UPK(f[0], f[1], acc[o][0]);
        UPK(f[2], f[3], acc[o][1]);
        UPK(f[4], f[5], acc[o][2]);
        UPK(f[6], f[7], acc[o][3]);
        int oo = oblk*16 + og*4 + o;
        float* d = &g_y_pre[((size_t)b*CC + oo)*PS + (ty0+py)*64 + tx0 + px8];
        *(float4*)d       = make_float4(f[0], f[1], f[2], f[3]);
        *(float4*)(d + 4) = make_float4(f[4], f[5], f[6], f[7]);
        int q = o >> 1;
#pragma unroll
        for (int j = 0; j < 8; j++) { ps[q] += f[j]; pss[q] += f[j]*f[j]; }
    }
#pragma unroll
    for (int q = 0; q < 2; q++)
#pragma unroll
        for (int off = 16; off; off >>= 1) {
            ps[q]  += __shfl_down_sync(0xffffffffu, ps[q],  off);
            pss[q] += __shfl_down_sync(0xffffffffu, pss[q], off);
        }
    int warp = tid >> 5, lane = tid & 31;
    if (lane == 0) {
        s_red[warp][0] = ps[0];  s_red[warp][1] = pss[0];
        s_red[warp][2] = ps[1];  s_red[warp][3] = pss[1];
    }
    __syncthreads();
    if (tid < 16) {
        int g = tid >> 1, isq = tid & 1;      // local group 0..7
        int ogq = g >> 1, gi = g & 1;
        float s = s_red[ogq*2][gi*2 + isq] + s_red[ogq*2 + 1][gi*2 + isq];
        g_part_y[((b*NG + oblk*8 + g)*8 + tileI)*2 + isq] = s;
    }
}

// ---------------- kernel 5: GN(y) + relu + final 1x1 + bias (stats folded in) ----------------
__global__ void __launch_bounds__(256) k_out(
        const float* __restrict__ wp2, const float* __restrict__ bp2,
        const float* __restrict__ gpw, const float* __restrict__ gpb,
        float* __restrict__ out) {
    __shared__ float scs[64], shs[64];
    int blk = blockIdx.x;
    int b = blk >> 4, p0 = (blk & 15) << 8;
    int tid = threadIdx.x;
    if (tid < 64) {
        int c = tid, g = c >> 1;
        float s = 0.f, ss = 0.f;
#pragma unroll
        for (int t = 0; t < 8; t++) {
            s  += g_part_y[((b*NG + g)*8 + t)*2 + 0];
            ss += g_part_y[((b*NG + g)*8 + t)*2 + 1];
        }
        float m = s * (1.f/8192.f);
        float var = ss * (1.f/8192.f) - m*m;
        float r = rsqrtf(var + 1e-5f);
        float scale = r * gpw[c];
        scs[c] = scale;
        shs[c] = gpb[c] - m*scale;
    }
    __syncthreads();
    float acc = bp2[0];
    const float* yp = g_y_pre + (size_t)(b*CC)*PS + p0 + tid;
#pragma unroll 8
    for (int o = 0; o < 64; o++) {
        float v = fmaxf(fmaf(yp[(size_t)o*PS], scs[o], shs[o]), 0.f);
        acc = fmaf(wp2[o], v, acc);
    }
    out[b*PS + p0 + tid] = acc;
}

// ---------------- launch ----------------
extern "C" void kernel_launch(void* const* d_in, const int* in_sizes, int n_in,
                              void* d_out, int out_size) {
    const float* tf  = (const float*)d_in[0];
    const float* sf  = (const float*)d_in[1];
    const float* wt  = (const float*)d_in[2];
    const float* gtw = (const float*)d_in[3];
    const float* gtb = (const float*)d_in[4];
    const float* ws  = (const float*)d_in[5];
    const float* gsw = (const float*)d_in[6];
    const float* gsb = (const float*)d_in[7];
    const float* wp1 = (const float*)d_in[8];
    const float* gpw = (const float*)d_in[9];
    const float* gpb = (const float*)d_in[10];
    const float* wp2 = (const float*)d_in[11];
    const float* bp2 = (const float*)d_in[12];
    float* out = (float*)d_out;

    k_template<<<128, 256>>>(tf, wt, gtw, gtb);          // launch 0
    k_search<<<dim3(32, 32), 256>>>(sf, ws);             // launch 1
    k_corr<<<2048, 256>>>(gsw, gsb);                     // launch 2
    k_conv3<<<dim3(8, 4, 32), 256>>>(wp1);               // launch 3  (ncu capture slot)
    k_out<<<512, 256>>>(wp2, bp2, gpw, gpb, out);        // launch 4
}

// round 12
// speedup vs baseline: 2.0709x; 1.2214x over previous
#include <cuda_runtime.h>
#include <cuda_bf16.h>
#include <cstdint>

#define B_ 32
#define CIN 256
#define CC 64
#define HS 64
#define PS 4096         // 64*64
#define HT 14
#define PT 196          // 14*14
#define NG 32           // groups (2 channels per group)

typedef unsigned long long ull;

// packed fp32x2 helpers (SASS FFMA2)
#define FMA2(d, a, b) asm("fma.rn.f32x2 %0, %1, %2, %0;" : "+l"(d) : "l"(a), "l"(b))
__device__ __forceinline__ ull PK(float lo, float hi) {
    ull r; asm("mov.b64 %0, {%1, %2};" : "=l"(r) : "f"(lo), "f"(hi)); return r;
}
__device__ __forceinline__ void UPK(float& lo, float& hi, ull v) {
    asm("mov.b64 {%0, %1}, %2;" : "=f"(lo), "=f"(hi) : "l"(v));
}

// cp.async helpers
__device__ __forceinline__ uint32_t smem_u32(const void* p) {
    return (uint32_t)__cvta_generic_to_shared(p);
}
__device__ __forceinline__ void cp16(uint32_t dst, const void* src) {
    asm volatile("cp.async.ca.shared.global [%0], [%1], 16;\n" :: "r"(dst), "l"(src));
}
__device__ __forceinline__ void cp16z(uint32_t dst, const void* src, uint32_t sz) {
    asm volatile("cp.async.ca.shared.global [%0], [%1], 16, %2;\n" :: "r"(dst), "l"(src), "r"(sz));
}
#define CP_COMMIT asm volatile("cp.async.commit_group;\n")
#define CP_WAIT0  asm volatile("cp.async.wait_group 0;\n")
#define CP_WAIT1  asm volatile("cp.async.wait_group 1;\n")

// ---- mma.sync / ldmatrix helpers (baseline sm_80 features, valid on sm_103) ----
__device__ __forceinline__ void ldsm4(uint32_t* r, uint32_t addr) {
    asm volatile("ldmatrix.sync.aligned.m8n8.x4.shared.b16 {%0,%1,%2,%3}, [%4];"
        : "=r"(r[0]), "=r"(r[1]), "=r"(r[2]), "=r"(r[3]) : "r"(addr));
}
__device__ __forceinline__ void ldsm2(uint32_t* r, uint32_t addr) {
    asm volatile("ldmatrix.sync.aligned.m8n8.x2.shared.b16 {%0,%1}, [%2];"
        : "=r"(r[0]), "=r"(r[1]) : "r"(addr));
}
__device__ __forceinline__ void mma16816(float* d, const uint32_t* a, const uint32_t* b) {
    asm volatile(
        "mma.sync.aligned.m16n8k16.row.col.f32.bf16.bf16.f32 "
        "{%0,%1,%2,%3}, {%4,%5,%6,%7}, {%8,%9}, {%0,%1,%2,%3};"
        : "+f"(d[0]), "+f"(d[1]), "+f"(d[2]), "+f"(d[3])
        : "r"(a[0]), "r"(a[1]), "r"(a[2]), "r"(a[3]), "r"(b[0]), "r"(b[1]));
}
#define SWZB(x) ((x) ^ (((x) >> 3) & 0x70))

// ---------------- device scratch (no allocations allowed) ----------------
__device__ float g_s_pre[B_*CC*PS];
__device__ float g_corr[B_*CC*PS];
__device__ float g_y_pre[B_*CC*PS];
__device__ __nv_bfloat16 g_bT_hi[(size_t)B_*PS*CC];   // px-major corr, hi part
__device__ __nv_bfloat16 g_bT_lo[(size_t)B_*PS*CC];   // px-major corr, lo part
__device__ float g_tglobal[B_*CC];
__device__ float g_tkernel[B_*CC*49];
__device__ float g_part_s[B_*NG*32*2];
__device__ float g_part_y[B_*CC*64*2];    // per (b,c,ytile*2+wn) sum/sumsq

// ---------------- kernel 1: template path ----------------
__global__ void __launch_bounds__(256) k_template(
        const float* __restrict__ tf, const float* __restrict__ wt,
        const float* __restrict__ gw, const float* __restrict__ gb) {
    __shared__ __align__(8) float wsm[256*18];
    __shared__ float pre[16*PT];
    __shared__ float s_mean[8], s_rstd[8];
    int b = blockIdx.x >> 2;
    int o0 = (blockIdx.x & 3) * 16;
    int tid = threadIdx.x;

    for (int idx = tid; idx < 4096; idx += 256) {
        int c = idx & 255, o = idx >> 8;
        wsm[c*18 + o] = wt[(o0+o)*CIN + c];
    }
    __syncthreads();

    if (tid < PT) {
        ull acc[8];
#pragma unroll
        for (int i = 0; i < 8; i++) acc[i] = 0ULL;
        const float* x = tf + (size_t)b*CIN*PT + tid;
#pragma unroll 4
        for (int c = 0; c < CIN; c++) {
            float xv = __ldg(x + c*PT);
            ull xd = PK(xv, xv);
#pragma unroll
            for (int i = 0; i < 8; i++) {
                ull w = *(const ull*)&wsm[c*18 + 2*i];
                FMA2(acc[i], w, xd);
            }
        }
#pragma unroll
        for (int i = 0; i < 8; i++) {
            float f0, f1; UPK(f0, f1, acc[i]);
            pre[(2*i)*PT + tid]   = f0;
            pre[(2*i+1)*PT + tid] = f1;
        }
    }
    __syncthreads();

    int warp = tid >> 5, lane = tid & 31;
    {
        int g = warp;
        float s = 0.f, ss = 0.f;
        const float* base = pre + g*2*PT;
        for (int i = lane; i < 2*PT; i += 32) { float v = base[i]; s += v; ss += v*v; }
#pragma unroll
        for (int off = 16; off; off >>= 1) {
            s  += __shfl_down_sync(0xffffffffu, s,  off);
            ss += __shfl_down_sync(0xffffffffu, ss, off);
        }
        if (lane == 0) {
            float m = s / (float)(2*PT);
            float var = ss / (float)(2*PT) - m*m;
            s_mean[g] = m; s_rstd[g] = rsqrtf(var + 1e-5f);
        }
    }
    __syncthreads();

    for (int idx = tid; idx < 16*PT; idx += 256) {
        int c = idx / PT; int g = c >> 1;
        float v = fmaf((pre[idx] - s_mean[g]) * s_rstd[g], gw[o0+c], gb[o0+c]);
        pre[idx] = fmaxf(v, 0.f);
    }
    __syncthreads();

    for (int c = warp; c < 16; c += 8) {
        float s = 0.f;
        for (int i = lane; i < PT; i += 32) s += pre[c*PT + i];
#pragma unroll
        for (int off = 16; off; off >>= 1) s += __shfl_down_sync(0xffffffffu, s, off);
        if (lane == 0) g_tglobal[b*CC + o0 + c] = s * (1.f/(float)PT);
    }
    for (int idx = tid; idx < 16*49; idx += 256) {
        int c = idx / 49, k = idx % 49, kh = k / 7, kw = k % 7;
        const float* p = pre + c*PT + (2*kh)*HT + 2*kw;
        g_tkernel[(b*CC + o0 + c)*49 + k] = 0.25f*(p[0] + p[1] + p[HT] + p[HT+1]);
    }
}

// ---------------- kernel 2: conv1x1 search GEMM, cp.async pipelined ----------------
__global__ void __launch_bounds__(256) k_search(const float* __restrict__ sf,
                                                const float* __restrict__ ws) {
    __shared__ __align__(16) float As[2][2048];
    __shared__ __align__(16) float Bs[2][4096];
    int tile = blockIdx.x, b = blockIdx.y;
    int tid = threadIdx.x;
    int tx = tid & 31, ty = tid >> 5;

    auto issue = [&](int s, int buf) {
        int k0 = s * 32;
#pragma unroll
        for (int i = 0; i < 4; i++) {
            int t = tid*4 + i;
            int kk = t >> 5, j4 = (t & 31) << 2;
            cp16(smem_u32(&Bs[buf][kk*128 + j4]),
                 sf + ((size_t)b*CIN + k0 + kk)*PS + tile*128 + j4);
        }
#pragma unroll
        for (int i = 0; i < 2; i++) {
            int slot = tid*2 + i;
            int o = slot >> 3, c4 = (slot & 7) << 2;
            cp16(smem_u32(&As[buf][o*32 + c4]), ws + o*CIN + k0 + c4);
        }
        CP_COMMIT;
    };

    ull acc[8][2];
#pragma unroll
    for (int i = 0; i < 8; i++) { acc[i][0] = 0ULL; acc[i][1] = 0ULL; }

    issue(0, 0);
    for (int s = 0; s < 8; s++) {
        int cur = s & 1;
        if (s < 7) { issue(s+1, 1-cur); CP_WAIT1; }
        else       { CP_WAIT0; }
        __syncthreads();
#pragma unroll
        for (int kk = 0; kk < 32; kk++) {
            float4 bv = *(const float4*)&Bs[cur][kk*128 + tx*4];
            ull b0 = PK(bv.x, bv.y), b1 = PK(bv.z, bv.w);
#pragma unroll
            for (int i = 0; i < 8; i++) {
                float w = As[cur][(ty*8 + i)*32 + kk];
                ull a = PK(w, w);
                FMA2(acc[i][0], a, b0);
                FMA2(acc[i][1], a, b1);
            }
        }
        __syncthreads();
    }

    float gs[4], gss[4];
#pragma unroll
    for (int q = 0; q < 4; q++) { gs[q] = 0.f; gss[q] = 0.f; }
#pragma unroll
    for (int i = 0; i < 8; i++) {
        int o = ty*8 + i;
        float f0, f1, f2, f3;
        UPK(f0, f1, acc[i][0]);
        UPK(f2, f3, acc[i][1]);
        *(float4*)&g_s_pre[((size_t)b*CC + o)*PS + tile*128 + tx*4] =
            make_float4(f0, f1, f2, f3);
        int q = i >> 1;
        gs[q]  += f0 + f1 + f2 + f3;
        gss[q] += f0*f0 + f1*f1 + f2*f2 + f3*f3;
    }
#pragma unroll
    for (int q = 0; q < 4; q++) {
#pragma unroll
        for (int off = 16; off; off >>= 1) {
            gs[q]  += __shfl_down_sync(0xffffffffu, gs[q],  off);
            gss[q] += __shfl_down_sync(0xffffffffu, gss[q], off);
        }
    }
    if (tx == 0) {
#pragma unroll
        for (int q = 0; q < 4; q++) {
            int g = ty*4 + q;
            g_part_s[((b*NG + g)*32 + tile)*2 + 0] = gs[q];
            g_part_s[((b*NG + g)*32 + tile)*2 + 1] = gss[q];
        }
    }
}

// ---------------- kernel 3: correlation (GN stats folded in) ----------------
__global__ void __launch_bounds__(256) k_corr(const float* __restrict__ gsw,
                                              const float* __restrict__ gsb) {
    __shared__ float tile[70*72];
    __shared__ float tk[49];
    __shared__ float s_scsh[2];
    int bc = blockIdx.x;
    int b = bc >> 6, c = bc & 63, g = c >> 1;
    int tid = threadIdx.x;
    if (tid < 32) {
        float s  = g_part_s[((b*NG + g)*32 + tid)*2 + 0];
        float ss = g_part_s[((b*NG + g)*32 + tid)*2 + 1];
#pragma unroll
        for (int off = 16; off; off >>= 1) {
            s  += __shfl_down_sync(0xffffffffu, s,  off);
            ss += __shfl_down_sync(0xffffffffu, ss, off);
        }
        if (tid == 0) {
            float m = s * (1.f/8192.f);
            float var = ss * (1.f/8192.f) - m*m;
            float r = rsqrtf(var + 1e-5f);
            float scale = r * gsw[c];
            s_scsh[0] = scale;
            s_scsh[1] = gsb[c] - m*scale;
        }
    }
    if (tid < 49) tk[tid] = g_tkernel[bc*49 + tid];
    __syncthreads();
    float sc = s_scsh[0], sh = s_scsh[1], tg = g_tglobal[bc];

    const float* sp = g_s_pre + (size_t)bc*PS;
    for (int idx = tid; idx < 4900; idx += 256) {
        int rr = idx / 70, col = idx - rr*70;
        int r = rr - 3, cx = col - 3;
        float v = 0.f;
        if ((unsigned)r < 64u && (unsigned)cx < 64u)
            v = fmaxf(fmaf(sp[r*64 + cx], sc, sh), 0.f);
        tile[rr*72 + col] = v;
    }
    __syncthreads();
    float* dst = g_corr + (size_t)bc*PS;
#pragma unroll
    for (int it = 0; it < 2; it++) {
        int u = tid + it*256;
        int y = u >> 3, x8 = (u & 7) << 3;
        float a[8];
#pragma unroll
        for (int j = 0; j < 8; j++) a[j] = 0.f;
#pragma unroll
        for (int kh = 0; kh < 7; kh++) {
            const float* row = tile + (y+kh)*72 + x8;
            float rv[16];
            *(float4*)&rv[0]  = *(const float4*)(row);
            *(float4*)&rv[4]  = *(const float4*)(row + 4);
            *(float4*)&rv[8]  = *(const float4*)(row + 8);
            *(float4*)&rv[12] = *(const float4*)(row + 12);
            if (kh == 3) {
#pragma unroll
                for (int j = 0; j < 8; j++) a[j] = fmaf(tg, rv[j+3], a[j]);
            }
#pragma unroll
            for (int kw = 0; kw < 7; kw++) {
                float w = tk[kh*7 + kw];
#pragma unroll
                for (int j = 0; j < 8; j++) a[j] = fmaf(w, rv[kw + j], a[j]);
            }
        }
        float* d = dst + y*64 + x8;
        *(float4*)d       = make_float4(a[0], a[1], a[2], a[3]);
        *(float4*)(d + 4) = make_float4(a[4], a[5], a[6], a[7]);
    }
}

// ---------------- kernel 4: transpose corr -> px-major bf16 hi/lo ----------------
__global__ void __launch_bounds__(256) k_tr() {
    __shared__ float ts[64*133];
    int blk = blockIdx.x;
    int b = blk >> 5, p0 = (blk & 31) << 7;
    int tid = threadIdx.x;
#pragma unroll
    for (int i = 0; i < 8; i++) {
        int idx = tid + i*256;              // 0..2047
        int c = idx >> 5, j4 = (idx & 31) << 2;
        float4 v = *(const float4*)&g_corr[((size_t)(b*64 + c))*PS + p0 + j4];
        float* t = &ts[c*133 + j4];
        t[0] = v.x; t[1] = v.y; t[2] = v.z; t[3] = v.w;
    }
    __syncthreads();
    int px = tid >> 1, ch = (tid & 1) * 32;
    size_t P = (size_t)b*PS + p0 + px;
    unsigned short hv[32], lv[32];
#pragma unroll
    for (int cc = 0; cc < 32; cc++) {
        float v = ts[(ch + cc)*133 + px];
        __nv_bfloat16 h = __float2bfloat16(v);
        float hf = __bfloat162float(h);
        __nv_bfloat16 l = __float2bfloat16(v - hf);
        hv[cc] = *(unsigned short*)&h;
        lv[cc] = *(unsigned short*)&l;
    }
    uint4* dh = (uint4*)(g_bT_hi + P*64 + ch);
    uint4* dl = (uint4*)(g_bT_lo + P*64 + ch);
#pragma unroll
    for (int q = 0; q < 4; q++) {
        uint4 u, w;
        u.x = hv[q*8+0] | (hv[q*8+1] << 16); u.y = hv[q*8+2] | (hv[q*8+3] << 16);
        u.z = hv[q*8+4] | (hv[q*8+5] << 16); u.w = hv[q*8+6] | (hv[q*8+7] << 16);
        w.x = lv[q*8+0] | (lv[q*8+1] << 16); w.y = lv[q*8+2] | (lv[q*8+3] << 16);
        w.z = lv[q*8+4] | (lv[q*8+5] << 16); w.w = lv[q*8+6] | (lv[q*8+7] << 16);
        dh[q] = u; dl[q] = w;
    }
}

// ---------------- kernel 5: conv3x3 via mma.sync (9 shifted GEMMs, split-bf16) ----------------
// Persistent 148 blocks, 256 thr (8 warps = 4 M-tiles x 2 N-tiles).
// Block tile: 64 out-ch x 128 px (2 y-rows). W hi/lo resident (144K),
// X halo tile [2 parts][4 srows][66 slots][64 c] (67.5K) via cp.async zfill.
#define W_BYTES   147456        // 2 parts * 9 taps * 64o*128B
#define W_PART    73728
#define X_PART    33792         // 264 rows * 128B
#define CMMA_SMEM (W_BYTES + 2*X_PART + 128)

__global__ void __launch_bounds__(256) k_cmma(const float* __restrict__ wp1) {
    extern __shared__ char dyn[];
    uint32_t dynb = smem_u32(dyn);
    uint32_t Wb = (dynb + 127) & ~127u;
    uint32_t Xb = Wb + W_BYTES;
    char* Wg = dyn + (Wb - dynb);
    int tid = threadIdx.x;
    int wid = tid >> 5, lane = tid & 31;

    // W prep: bf16 hi/lo, per-tap [64o][64c] swizzled row-major tiles
    // wp1 has 64*64*9 = 36864 floats  (FIX: was 9216)
    for (int idx = tid; idx < 36864; idx += 256) {
        float w = __ldg(wp1 + idx);
        int o = idx / 576, rem = idx - o*576;
        int c = rem / 9, k = rem - c*9;           // k = dy*3+dx
        __nv_bfloat16 h = __float2bfloat16(w);
        float hf = __bfloat162float(h);
        __nv_bfloat16 l = __float2bfloat16(w - hf);
        uint32_t off = SWZB((uint32_t)(o*128 + c*2));
        *(__nv_bfloat16*)(Wg + k*8192 + off) = h;
        *(__nv_bfloat16*)(Wg + W_PART + k*8192 + off) = l;
    }

    int wm = wid & 3, wn = wid >> 2;
    int o0 = wm << 4;
    int arow = lane & 15;
    int achunk = (lane & 16) ? 16 : 0;
    int brlane = lane & 7;
    int bchunk = (lane & 8) ? 16 : 0;

    for (int t = blockIdx.x; t < 1024; t += gridDim.x) {
        int b = t >> 5, yt = t & 31, y0 = yt << 1;
        __syncthreads();      // previous compute done before X overwrite; first iter: W ready

        // X halo load: 2 parts x 4 srows x 66 slots x 8 units of 16B
        for (int idx = tid; idx < 4224; idx += 256) {
            int part = idx / 2112, rem = idx - part*2112;
            int srow = rem / 528, r3 = rem - srow*528;
            int slot = r3 >> 3, unit = r3 & 7;
            int y = y0 + srow - 1, x = slot - 1;
            bool ok = ((unsigned)y < 64u) && ((unsigned)x < 64u);
            int yy = ok ? y : 0, xx = ok ? x : 0;
            const __nv_bfloat16* src = (part ? g_bT_lo : g_bT_hi)
                + (((size_t)b*PS + yy*64 + xx) << 6) + unit*8;
            uint32_t dst = Xb + part*X_PART + SWZB((uint32_t)(((srow*66 + slot) << 7) + unit*16));
            cp16z(dst, src, ok ? 16u : 0u);
        }
        CP_COMMIT; CP_WAIT0;
        __syncthreads();

        float acc[8][4];
#pragma unroll
        for (int i = 0; i < 8; i++)
#pragma unroll
            for (int j = 0; j < 4; j++) acc[i][j] = 0.f;

        for (int dy = 0; dy < 3; dy++) {
            int srow = wn + dy;
            for (int dx = 0; dx < 3; dx++) {
                uint32_t wtap = Wb + (dy*3 + dx)*8192;
                for (int ks = 0; ks < 4; ks++) {
                    uint32_t ah[4], al[4];
                    // FIX: include warp's M offset o0 in the A row address
                    uint32_t aoff = SWZB((uint32_t)((o0 + arow)*128 + ks*32 + achunk));
                    ldsm4(ah, wtap + aoff);
                    ldsm4(al, wtap + W_PART + aoff);
#pragma unroll
                    for (int nt = 0; nt < 8; nt++) {
                        int slot = nt*8 + dx + brlane;
                        uint32_t boff = SWZB((uint32_t)(((srow*66 + slot) << 7) + ks*32 + bchunk));
                        uint32_t bh[2], bl[2];
                        ldsm2(bh, Xb + boff);
                        ldsm2(bl, Xb + X_PART + boff);
                        mma16816(acc[nt], ah, bh);
                        mma16816(acc[nt], ah, bl);
                        mma16816(acc[nt], al, bh);
                    }
                }
            }
        }

        // epilogue: direct STG from fragments + GN partials
        int q = lane >> 2, tx2 = (lane & 3) << 1;
        int y = y0 + wn;
        int oa = o0 + q, ob = oa + 8;
        float* da = &g_y_pre[((size_t)(b*64 + oa))*PS + y*64];
        float* db = &g_y_pre[((size_t)(b*64 + ob))*PS + y*64];
        float s0 = 0.f, ss0 = 0.f, s1 = 0.f, ss1 = 0.f;
#pragma unroll
        for (int nt = 0; nt < 8; nt++) {
            int x = nt*8 + tx2;
            *(float2*)(da + x) = make_float2(acc[nt][0], acc[nt][1]);
            *(float2*)(db + x) = make_float2(acc[nt][2], acc[nt][3]);
            s0 += acc[nt][0] + acc[nt][1];
            ss0 += acc[nt][0]*acc[nt][0] + acc[nt][1]*acc[nt][1];
            s1 += acc[nt][2] + acc[nt][3];
            ss1 += acc[nt][2]*acc[nt][2] + acc[nt][3]*acc[nt][3];
        }
        s0 += __shfl_xor_sync(0xffffffffu, s0, 1); s0 += __shfl_xor_sync(0xffffffffu, s0, 2);
        ss0 += __shfl_xor_sync(0xffffffffu, ss0, 1); ss0 += __shfl_xor_sync(0xffffffffu, ss0, 2);
        s1 += __shfl_xor_sync(0xffffffffu, s1, 1); s1 += __shfl_xor_sync(0xffffffffu, s1, 2);
        ss1 += __shfl_xor_sync(0xffffffffu, ss1, 1); ss1 += __shfl_xor_sync(0xffffffffu, ss1, 2);
        if ((lane & 3) == 0) {
            int ti = (yt << 1) + wn;
            g_part_y[((b*64 + oa)*64 + ti)*2 + 0] = s0;
            g_part_y[((b*64 + oa)*64 + ti)*2 + 1] = ss0;
            g_part_y[((b*64 + ob)*64 + ti)*2 + 0] = s1;
            g_part_y[((b*64 + ob)*64 + ti)*2 + 1] = ss1;
        }
    }
}

// ---------------- kernel 6: GN(y) + relu + final 1x1 + bias ----------------
__global__ void __launch_bounds__(256) k_out(
        const float* __restrict__ wp2, const float* __restrict__ bp2,
        const float* __restrict__ gpw, const float* __restrict__ gpb,
        float* __restrict__ out) {
    __shared__ float su[64], sq[64], scs[64], shs[64];
    int blk = blockIdx.x;
    int b = blk >> 4, p0 = (blk & 15) << 8;
    int tid = threadIdx.x;
    if (tid < 64) {
        int c = tid;
        float s = 0.f, ss = 0.f;
#pragma unroll 8
        for (int t = 0; t < 64; t++) {
            s  += g_part_y[((b*64 + c)*64 + t)*2 + 0];
            ss += g_part_y[((b*64 + c)*64 + t)*2 + 1];
        }
        su[c] = s; sq[c] = ss;
    }
    __syncthreads();
    if (tid < 64) {
        int c = tid;
        float S = su[c] + su[c^1], SS = sq[c] + sq[c^1];
        float m = S * (1.f/8192.f);
        float var = SS * (1.f/8192.f) - m*m;
        float r = rsqrtf(var + 1e-5f);
        float scale = r * gpw[c];
        scs[c] = scale;
        shs[c] = gpb[c] - m*scale;
    }
    __syncthreads();
    float acc = bp2[0];
    const float* yp = g_y_pre + (size_t)(b*CC)*PS + p0 + tid;
#pragma unroll 8
    for (int o = 0; o < 64; o++) {
        float v = fmaxf(fmaf(yp[(size_t)o*PS], scs[o], shs[o]), 0.f);
        acc = fmaf(wp2[o], v, acc);
    }
    out[b*PS + p0 + tid] = acc;
}

// ---------------- launch ----------------
extern "C" void kernel_launch(void* const* d_in, const int* in_sizes, int n_in,
                              void* d_out, int out_size) {
    const float* tf  = (const float*)d_in[0];
    const float* sf  = (const float*)d_in[1];
    const float* wt  = (const float*)d_in[2];
    const float* gtw = (const float*)d_in[3];
    const float* gtb = (const float*)d_in[4];
    const float* ws  = (const float*)d_in[5];
    const float* gsw = (const float*)d_in[6];
    const float* gsb = (const float*)d_in[7];
    const float* wp1 = (const float*)d_in[8];
    const float* gpw = (const float*)d_in[9];
    const float* gpb = (const float*)d_in[10];
    const float* wp2 = (const float*)d_in[11];
    const float* bp2 = (const float*)d_in[12];
    float* out = (float*)d_out;

    cudaFuncSetAttribute(k_cmma, cudaFuncAttributeMaxDynamicSharedMemorySize, CMMA_SMEM);

    k_template<<<128, 256>>>(tf, wt, gtw, gtb);          // 0
    k_search<<<dim3(32, 32), 256>>>(sf, ws);             // 1
    k_corr<<<2048, 256>>>(gsw, gsb);                     // 2
    k_tr<<<1024, 256>>>();                               // 3
    k_cmma<<<148, 256, CMMA_SMEM>>>(wp1);                // 4
    k_out<<<512, 256>>>(wp2, bp2, gpw, gpb, out);        // 5
}

// round 14
// speedup vs baseline: 2.3499x; 1.1347x over previous
#include <cuda_runtime.h>
#include <cuda_bf16.h>
#include <cstdint>

#define B_ 32
#define CIN 256
#define CC 64
#define HS 64
#define PS 4096         // 64*64
#define HT 14
#define PT 196          // 14*14
#define NG 32           // groups (2 channels per group)

typedef unsigned long long ull;

// packed fp32x2 helpers (SASS FFMA2)
#define FMA2(d, a, b) asm("fma.rn.f32x2 %0, %1, %2, %0;" : "+l"(d) : "l"(a), "l"(b))
__device__ __forceinline__ ull PK(float lo, float hi) {
    ull r; asm("mov.b64 %0, {%1, %2};" : "=l"(r) : "f"(lo), "f"(hi)); return r;
}
__device__ __forceinline__ void UPK(float& lo, float& hi, ull v) {
    asm("mov.b64 {%0, %1}, %2;" : "=f"(lo), "=f"(hi) : "l"(v));
}

// cp.async helpers
__device__ __forceinline__ uint32_t smem_u32(const void* p) {
    return (uint32_t)__cvta_generic_to_shared(p);
}
__device__ __forceinline__ void cp16(uint32_t dst, const void* src) {
    asm volatile("cp.async.ca.shared.global [%0], [%1], 16;\n" :: "r"(dst), "l"(src));
}
__device__ __forceinline__ void cp16z(uint32_t dst, const void* src, uint32_t sz) {
    asm volatile("cp.async.ca.shared.global [%0], [%1], 16, %2;\n" :: "r"(dst), "l"(src), "r"(sz));
}
#define CP_COMMIT asm volatile("cp.async.commit_group;\n")
#define CP_WAIT0  asm volatile("cp.async.wait_group 0;\n")
#define CP_WAIT1  asm volatile("cp.async.wait_group 1;\n")

// ---- mma.sync / ldmatrix helpers ----
__device__ __forceinline__ void ldsm4(uint32_t* r, uint32_t addr) {
    asm volatile("ldmatrix.sync.aligned.m8n8.x4.shared.b16 {%0,%1,%2,%3}, [%4];"
        : "=r"(r[0]), "=r"(r[1]), "=r"(r[2]), "=r"(r[3]) : "r"(addr));
}
__device__ __forceinline__ void mma16816(float* d, const uint32_t* a, const uint32_t* b) {
    asm volatile(
        "mma.sync.aligned.m16n8k16.row.col.f32.bf16.bf16.f32 "
        "{%0,%1,%2,%3}, {%4,%5,%6,%7}, {%8,%9}, {%0,%1,%2,%3};"
        : "+f"(d[0]), "+f"(d[1]), "+f"(d[2]), "+f"(d[3])
        : "r"(a[0]), "r"(a[1]), "r"(a[2]), "r"(a[3]), "r"(b[0]), "r"(b[1]));
}
#define SWZB(x) ((x) ^ (((x) >> 3) & 0x70))

// ---------------- device scratch ----------------
__device__ float g_s_pre[B_*CC*PS];
__device__ float g_corr[B_*CC*PS];
__device__ float g_y_pre[B_*CC*PS];
__device__ __nv_bfloat16 g_bT_hi[(size_t)B_*PS*CC];
__device__ __nv_bfloat16 g_bT_lo[(size_t)B_*PS*CC];
__device__ float g_tglobal[B_*CC];
__device__ float g_tkernel[B_*CC*49];
__device__ float g_part_s[B_*NG*32*2];
__device__ float g_part_y[B_*CC*64*2];

// ---------------- kernel 1: FUSED conv1x1-search GEMM + template path ----------------
// grid 1152: blocks 0..1023 = search (tile = blk&31, b = blk>>5);
//            blocks 1024..1151 = template (b = tb>>2, o0 = (tb&3)*16).
__global__ void __launch_bounds__(256) k_fused(
        const float* __restrict__ sf, const float* __restrict__ ws,
        const float* __restrict__ tf, const float* __restrict__ wt,
        const float* __restrict__ gw, const float* __restrict__ gb) {
    __shared__ __align__(16) char buf[49152];
    int tid = threadIdx.x;
    int blk = blockIdx.x;

    if (blk < 1024) {
        // ---- search path ----
        float* As0 = (float*)buf;              // [2][2048]
        float* Bs0 = (float*)(buf + 16384);    // [2][4096]
        int tile = blk & 31, b = blk >> 5;
        int tx = tid & 31, ty = tid >> 5;

        auto issue = [&](int s, int bufi) {
            int k0 = s * 32;
            float* Bs = Bs0 + bufi*4096;
            float* As = As0 + bufi*2048;
#pragma unroll
            for (int i = 0; i < 4; i++) {
                int t = tid*4 + i;
                int kk = t >> 5, j4 = (t & 31) << 2;
                cp16(smem_u32(Bs + kk*128 + j4),
                     sf + ((size_t)b*CIN + k0 + kk)*PS + tile*128 + j4);
            }
#pragma unroll
            for (int i = 0; i < 2; i++) {
                int slot = tid*2 + i;
                int o = slot >> 3, c4 = (slot & 7) << 2;
                cp16(smem_u32(As + o*32 + c4), ws + o*CIN + k0 + c4);
            }
            CP_COMMIT;
        };

        ull acc[8][2];
#pragma unroll
        for (int i = 0; i < 8; i++) { acc[i][0] = 0ULL; acc[i][1] = 0ULL; }

        issue(0, 0);
        for (int s = 0; s < 8; s++) {
            int cur = s & 1;
            if (s < 7) { issue(s+1, 1-cur); CP_WAIT1; }
            else       { CP_WAIT0; }
            __syncthreads();
            float* Bs = Bs0 + cur*4096;
            float* As = As0 + cur*2048;
#pragma unroll
            for (int kk = 0; kk < 32; kk++) {
                float4 bv = *(const float4*)(Bs + kk*128 + tx*4);
                ull b0 = PK(bv.x, bv.y), b1 = PK(bv.z, bv.w);
#pragma unroll
                for (int i = 0; i < 8; i++) {
                    float w = As[(ty*8 + i)*32 + kk];
                    ull a = PK(w, w);
                    FMA2(acc[i][0], a, b0);
                    FMA2(acc[i][1], a, b1);
                }
            }
            __syncthreads();
        }

        float gs[4], gss[4];
#pragma unroll
        for (int q = 0; q < 4; q++) { gs[q] = 0.f; gss[q] = 0.f; }
#pragma unroll
        for (int i = 0; i < 8; i++) {
            int o = ty*8 + i;
            float f0, f1, f2, f3;
            UPK(f0, f1, acc[i][0]);
            UPK(f2, f3, acc[i][1]);
            *(float4*)&g_s_pre[((size_t)b*CC + o)*PS + tile*128 + tx*4] =
                make_float4(f0, f1, f2, f3);
            int q = i >> 1;
            gs[q]  += f0 + f1 + f2 + f3;
            gss[q] += f0*f0 + f1*f1 + f2*f2 + f3*f3;
        }
#pragma unroll
        for (int q = 0; q < 4; q++) {
#pragma unroll
            for (int off = 16; off; off >>= 1) {
                gs[q]  += __shfl_down_sync(0xffffffffu, gs[q],  off);
                gss[q] += __shfl_down_sync(0xffffffffu, gss[q], off);
            }
        }
        if (tx == 0) {
#pragma unroll
            for (int q = 0; q < 4; q++) {
                int g = ty*4 + q;
                g_part_s[((b*NG + g)*32 + tile)*2 + 0] = gs[q];
                g_part_s[((b*NG + g)*32 + tile)*2 + 1] = gss[q];
            }
        }
        return;
    }

    // ---- template path ----
    {
        int tb = blk - 1024;
        int b = tb >> 2;
        int o0 = (tb & 3) * 16;
        float* wsm = (float*)buf;                    // [256*18]
        float* pre = (float*)(buf + 18432);          // [16*196]
        float* s_mean = (float*)(buf + 30976);       // [8]
        float* s_rstd = (float*)(buf + 31040);       // [8]

        for (int idx = tid; idx < 4096; idx += 256) {
            int c = idx & 255, o = idx >> 8;
            wsm[c*18 + o] = wt[(o0+o)*CIN + c];
        }
        __syncthreads();

        if (tid < PT) {
            ull acc[8];
#pragma unroll
            for (int i = 0; i < 8; i++) acc[i] = 0ULL;
            const float* x = tf + (size_t)b*CIN*PT + tid;
#pragma unroll 4
            for (int c = 0; c < CIN; c++) {
                float xv = __ldg(x + c*PT);
                ull xd = PK(xv, xv);
#pragma unroll
                for (int i = 0; i < 8; i++) {
                    ull w = *(const ull*)&wsm[c*18 + 2*i];
                    FMA2(acc[i], w, xd);
                }
            }
#pragma unroll
            for (int i = 0; i < 8; i++) {
                float f0, f1; UPK(f0, f1, acc[i]);
                pre[(2*i)*PT + tid]   = f0;
                pre[(2*i+1)*PT + tid] = f1;
            }
        }
        __syncthreads();

        int warp = tid >> 5, lane = tid & 31;
        {
            int g = warp;
            float s = 0.f, ss = 0.f;
            const float* base = pre + g*2*PT;
            for (int i = lane; i < 2*PT; i += 32) { float v = base[i]; s += v; ss += v*v; }
#pragma unroll
            for (int off = 16; off; off >>= 1) {
                s  += __shfl_down_sync(0xffffffffu, s,  off);
                ss += __shfl_down_sync(0xffffffffu, ss, off);
            }
            if (lane == 0) {
                float m = s / (float)(2*PT);
                float var = ss / (float)(2*PT) - m*m;
                s_mean[g] = m; s_rstd[g] = rsqrtf(var + 1e-5f);
            }
        }
        __syncthreads();

        for (int idx = tid; idx < 16*PT; idx += 256) {
            int c = idx / PT; int g = c >> 1;
            float v = fmaf((pre[idx] - s_mean[g]) * s_rstd[g], gw[o0+c], gb[o0+c]);
            pre[idx] = fmaxf(v, 0.f);
        }
        __syncthreads();

        for (int c = warp; c < 16; c += 8) {
            float s = 0.f;
            for (int i = lane; i < PT; i += 32) s += pre[c*PT + i];
#pragma unroll
            for (int off = 16; off; off >>= 1) s += __shfl_down_sync(0xffffffffu, s, off);
            if (lane == 0) g_tglobal[b*CC + o0 + c] = s * (1.f/(float)PT);
        }
        for (int idx = tid; idx < 16*49; idx += 256) {
            int c = idx / 49, k = idx % 49, kh = k / 7, kw = k % 7;
            const float* p = pre + c*PT + (2*kh)*HT + 2*kw;
            g_tkernel[(b*CC + o0 + c)*49 + k] = 0.25f*(p[0] + p[1] + p[HT] + p[HT+1]);
        }
    }
}

// ---------------- kernel 2: correlation (GN stats folded in) ----------------
__global__ void __launch_bounds__(256) k_corr(const float* __restrict__ gsw,
                                              const float* __restrict__ gsb) {
    __shared__ float tile[70*72];
    __shared__ float tk[49];
    __shared__ float s_scsh[2];
    int bc = blockIdx.x;
    int b = bc >> 6, c = bc & 63, g = c >> 1;
    int tid = threadIdx.x;
    if (tid < 32) {
        float s  = g_part_s[((b*NG + g)*32 + tid)*2 + 0];
        float ss = g_part_s[((b*NG + g)*32 + tid)*2 + 1];
#pragma unroll
        for (int off = 16; off; off >>= 1) {
            s  += __shfl_down_sync(0xffffffffu, s,  off);
            ss += __shfl_down_sync(0xffffffffu, ss, off);
        }
        if (tid == 0) {
            float m = s * (1.f/8192.f);
            float var = ss * (1.f/8192.f) - m*m;
            float r = rsqrtf(var + 1e-5f);
            float scale = r * gsw[c];
            s_scsh[0] = scale;
            s_scsh[1] = gsb[c] - m*scale;
        }
    }
    if (tid < 49) tk[tid] = g_tkernel[bc*49 + tid];
    __syncthreads();
    float sc = s_scsh[0], sh = s_scsh[1], tg = g_tglobal[bc];

    const float* sp = g_s_pre + (size_t)bc*PS;
    for (int idx = tid; idx < 4900; idx += 256) {
        int rr = idx / 70, col = idx - rr*70;
        int r = rr - 3, cx = col - 3;
        float v = 0.f;
        if ((unsigned)r < 64u && (unsigned)cx < 64u)
            v = fmaxf(fmaf(sp[r*64 + cx], sc, sh), 0.f);
        tile[rr*72 + col] = v;
    }
    __syncthreads();
    float* dst = g_corr + (size_t)bc*PS;
#pragma unroll
    for (int it = 0; it < 2; it++) {
        int u = tid + it*256;
        int y = u >> 3, x8 = (u & 7) << 3;
        float a[8];
#pragma unroll
        for (int j = 0; j < 8; j++) a[j] = 0.f;
#pragma unroll
        for (int kh = 0; kh < 7; kh++) {
            const float* row = tile + (y+kh)*72 + x8;
            float rv[16];
            *(float4*)&rv[0]  = *(const float4*)(row);
            *(float4*)&rv[4]  = *(const float4*)(row + 4);
            *(float4*)&rv[8]  = *(const float4*)(row + 8);
            *(float4*)&rv[12] = *(const float4*)(row + 12);
            if (kh == 3) {
#pragma unroll
                for (int j = 0; j < 8; j++) a[j] = fmaf(tg, rv[j+3], a[j]);
            }
#pragma unroll
            for (int kw = 0; kw < 7; kw++) {
                float w = tk[kh*7 + kw];
#pragma unroll
                for (int j = 0; j < 8; j++) a[j] = fmaf(w, rv[kw + j], a[j]);
            }
        }
        float* d = dst + y*64 + x8;
        *(float4*)d       = make_float4(a[0], a[1], a[2], a[3]);
        *(float4*)(d + 4) = make_float4(a[4], a[5], a[6], a[7]);
    }
}

// ---------------- kernel 3: transpose corr -> px-major bf16 hi/lo ----------------
__global__ void __launch_bounds__(256) k_tr() {
    __shared__ float ts[64*133];
    int blk = blockIdx.x;
    int b = blk >> 5, p0 = (blk & 31) << 7;
    int tid = threadIdx.x;
#pragma unroll
    for (int i = 0; i < 8; i++) {
        int idx = tid + i*256;
        int c = idx >> 5, j4 = (idx & 31) << 2;
        float4 v = *(const float4*)&g_corr[((size_t)(b*64 + c))*PS + p0 + j4];
        float* t = &ts[c*133 + j4];
        t[0] = v.x; t[1] = v.y; t[2] = v.z; t[3] = v.w;
    }
    __syncthreads();
    int px = tid >> 1, ch = (tid & 1) * 32;
    size_t P = (size_t)b*PS + p0 + px;
    unsigned short hv[32], lv[32];
#pragma unroll
    for (int cc = 0; cc < 32; cc++) {
        float v = ts[(ch + cc)*133 + px];
        __nv_bfloat16 h = __float2bfloat16(v);
        float hf = __bfloat162float(h);
        __nv_bfloat16 l = __float2bfloat16(v - hf);
        hv[cc] = *(unsigned short*)&h;
        lv[cc] = *(unsigned short*)&l;
    }
    uint4* dh = (uint4*)(g_bT_hi + P*64 + ch);
    uint4* dl = (uint4*)(g_bT_lo + P*64 + ch);
#pragma unroll
    for (int q = 0; q < 4; q++) {
        uint4 u, w;
        u.x = hv[q*8+0] | (hv[q*8+1] << 16); u.y = hv[q*8+2] | (hv[q*8+3] << 16);
        u.z = hv[q*8+4] | (hv[q*8+5] << 16); u.w = hv[q*8+6] | (hv[q*8+7] << 16);
        w.x = lv[q*8+0] | (lv[q*8+1] << 16); w.y = lv[q*8+2] | (lv[q*8+3] << 16);
        w.z = lv[q*8+4] | (lv[q*8+5] << 16); w.w = lv[q*8+6] | (lv[q*8+7] << 16);
        dh[q] = u; dl[q] = w;
    }
}

// ---------------- kernel 4: conv3x3 via mma.sync, pipelined ----------------
#define W_BYTES   147456
#define W_PART    73728
#define X_PART    33792
#define CMMA_SMEM (W_BYTES + 2*X_PART + 128)

__global__ void __launch_bounds__(256) k_cmma(const float* __restrict__ wp1) {
    extern __shared__ char dyn[];
    uint32_t dynb = smem_u32(dyn);
    uint32_t Wb = (dynb + 127) & ~127u;
    uint32_t Xb = Wb + W_BYTES;
    char* Wg = dyn + (Wb - dynb);
    int tid = threadIdx.x;
    int wid = tid >> 5, lane = tid & 31;

    // W prep: bf16 hi/lo, per-tap [64o][64c] swizzled (wp1 = 36864 floats)
    for (int idx = tid; idx < 36864; idx += 256) {
        float w = __ldg(wp1 + idx);
        int o = idx / 576, rem = idx - o*576;
        int c = rem / 9, k = rem - c*9;
        __nv_bfloat16 h = __float2bfloat16(w);
        float hf = __bfloat162float(h);
        __nv_bfloat16 l = __float2bfloat16(w - hf);
        uint32_t off = SWZB((uint32_t)(o*128 + c*2));
        *(__nv_bfloat16*)(Wg + k*8192 + off) = h;
        *(__nv_bfloat16*)(Wg + W_PART + k*8192 + off) = l;
    }

    int wm = wid & 3, wn = wid >> 2;
    int o0 = wm << 4;
    int arow = lane & 15;
    int achunk = (lane & 16) ? 16 : 0;
    // ldsm4 B lane mapping: lanes 0-15 -> nt, lanes 16-31 -> nt+1
    int brlane = lane & 7;
    int bsel8 = (lane >> 4) & 1;            // which nt of the pair
    int bchunk = (lane & 8) ? 16 : 0;

    auto issueX = [&](int t) {
        int b = t >> 5, y0 = (t & 31) << 1;
        for (int idx = tid; idx < 4224; idx += 256) {
            int part = idx / 2112, rem = idx - part*2112;
            int srow = rem / 528, r3 = rem - srow*528;
            int slot = r3 >> 3, unit = r3 & 7;
            int y = y0 + srow - 1, x = slot - 1;
            bool ok = ((unsigned)y < 64u) && ((unsigned)x < 64u);
            int yy = ok ? y : 0, xx = ok ? x : 0;
            const __nv_bfloat16* src = (part ? g_bT_lo : g_bT_hi)
                + (((size_t)b*PS + yy*64 + xx) << 6) + unit*8;
            uint32_t dst = Xb + part*X_PART + SWZB((uint32_t)(((srow*66 + slot) << 7) + unit*16));
            cp16z(dst, src, ok ? 16u : 0u);
        }
        CP_COMMIT;
    };

    int t0 = blockIdx.x;
    if (t0 < 1024) issueX(t0);
    __syncthreads();          // W stores visible (and X issued)

    for (int t = t0; t < 1024; t += gridDim.x) {
        int b = t >> 5, yt = t & 31, y0 = yt << 1;
        CP_WAIT0;
        __syncthreads();      // X ready for all warps

        float acc[8][4];
#pragma unroll
        for (int i = 0; i < 8; i++)
#pragma unroll
            for (int j = 0; j < 4; j++) acc[i][j] = 0.f;

        for (int dy = 0; dy < 3; dy++) {
            int srow = wn + dy;
            for (int dx = 0; dx < 3; dx++) {
                uint32_t wtap = Wb + (dy*3 + dx)*8192;
                for (int ks = 0; ks < 4; ks++) {
                    uint32_t ah[4], al[4];
                    uint32_t aoff = SWZB((uint32_t)((o0 + arow)*128 + ks*32 + achunk));
                    ldsm4(ah, wtap + aoff);
                    ldsm4(al, wtap + W_PART + aoff);
#pragma unroll
                    for (int nt2 = 0; nt2 < 4; nt2++) {
                        int slot = (nt2*2 + bsel8)*8 + dx + brlane;
                        uint32_t boff = SWZB((uint32_t)(((srow*66 + slot) << 7) + ks*32 + bchunk));
                        uint32_t bh[4], bl[4];
                        ldsm4(bh, Xb + boff);
                        ldsm4(bl, Xb + X_PART + boff);
                        mma16816(acc[nt2*2+0], ah, bh+0);
                        mma16816(acc[nt2*2+0], ah, bl+0);
                        mma16816(acc[nt2*2+0], al, bh+0);
                        mma16816(acc[nt2*2+1], ah, bh+2);
                        mma16816(acc[nt2*2+1], ah, bl+2);
                        mma16816(acc[nt2*2+1], al, bh+2);
                    }
                }
            }
        }
        __syncthreads();      // all warps done reading X

        int tn = t + gridDim.x;
        if (tn < 1024) issueX(tn);   // overlap next X load with epilogue

        // epilogue: direct STG from fragments + GN partials
        int q = lane >> 2, tx2 = (lane & 3) << 1;
        int y = y0 + wn;
        int oa = o0 + q, ob = oa + 8;
        float* da = &g_y_pre[((size_t)(b*64 + oa))*PS + y*64];
        float* db = &g_y_pre[((size_t)(b*64 + ob))*PS + y*64];
        float s0 = 0.f, ss0 = 0.f, s1 = 0.f, ss1 = 0.f;
#pragma unroll
        for (int nt = 0; nt < 8; nt++) {
            int x = nt*8 + tx2;
            *(float2*)(da + x) = make_float2(acc[nt][0], acc[nt][1]);
            *(float2*)(db + x) = make_float2(acc[nt][2], acc[nt][3]);
            s0 += acc[nt][0] + acc[nt][1];
            ss0 += acc[nt][0]*acc[nt][0] + acc[nt][1]*acc[nt][1];
            s1 += acc[nt][2] + acc[nt][3];
            ss1 += acc[nt][2]*acc[nt][2] + acc[nt][3]*acc[nt][3];
        }
        s0 += __shfl_xor_sync(0xffffffffu, s0, 1); s0 += __shfl_xor_sync(0xffffffffu, s0, 2);
        ss0 += __shfl_xor_sync(0xffffffffu, ss0, 1); ss0 += __shfl_xor_sync(0xffffffffu, ss0, 2);
        s1 += __shfl_xor_sync(0xffffffffu, s1, 1); s1 += __shfl_xor_sync(0xffffffffu, s1, 2);
        ss1 += __shfl_xor_sync(0xffffffffu, ss1, 1); ss1 += __shfl_xor_sync(0xffffffffu, ss1, 2);
        if ((lane & 3) == 0) {
            int ti = (yt << 1) + wn;
            g_part_y[((b*64 + oa)*64 + ti)*2 + 0] = s0;
            g_part_y[((b*64 + oa)*64 + ti)*2 + 1] = ss0;
            g_part_y[((b*64 + ob)*64 + ti)*2 + 0] = s1;
            g_part_y[((b*64 + ob)*64 + ti)*2 + 1] = ss1;
        }
    }
}

// ---------------- kernel 5: GN(y) + relu + final 1x1 + bias ----------------
__global__ void __launch_bounds__(256) k_out(
        const float* __restrict__ wp2, const float* __restrict__ bp2,
        const float* __restrict__ gpw, const float* __restrict__ gpb,
        float* __restrict__ out) {
    __shared__ float su[64], sq[64], scs[64], shs[64];
    int blk = blockIdx.x;
    int b = blk >> 4, p0 = (blk & 15) << 8;
    int tid = threadIdx.x;
    if (tid < 64) {
        int c = tid;
        float s = 0.f, ss = 0.f;
#pragma unroll 8
        for (int t = 0; t < 64; t++) {
            s  += g_part_y[((b*64 + c)*64 + t)*2 + 0];
            ss += g_part_y[((b*64 + c)*64 + t)*2 + 1];
        }
        su[c] = s; sq[c] = ss;
    }
    __syncthreads();
    if (tid < 64) {
        int c = tid;
        float S = su[c] + su[c^1], SS = sq[c] + sq[c^1];
        float m = S * (1.f/8192.f);
        float var = SS * (1.f/8192.f) - m*m;
        float r = rsqrtf(var + 1e-5f);
        float scale = r * gpw[c];
        scs[c] = scale;
        shs[c] = gpb[c] - m*scale;
    }
    __syncthreads();
    float acc = bp2[0];
    const float* yp = g_y_pre + (size_t)(b*CC)*PS + p0 + tid;
#pragma unroll 8
    for (int o = 0; o < 64; o++) {
        float v = fmaxf(fmaf(yp[(size_t)o*PS], scs[o], shs[o]), 0.f);
        acc = fmaf(wp2[o], v, acc);
    }
    out[b*PS + p0 + tid] = acc;
}

// ---------------- launch ----------------
extern "C" void kernel_launch(void* const* d_in, const int* in_sizes, int n_in,
                              void* d_out, int out_size) {
    const float* tf  = (const float*)d_in[0];
    const float* sf  = (const float*)d_in[1];
    const float* wt  = (const float*)d_in[2];
    const float* gtw = (const float*)d_in[3];
    const float* gtb = (const float*)d_in[4];
    const float* ws  = (const float*)d_in[5];
    const float* gsw = (const float*)d_in[6];
    const float* gsb = (const float*)d_in[7];
    const float* wp1 = (const float*)d_in[8];
    const float* gpw = (const float*)d_in[9];
    const float* gpb = (const float*)d_in[10];
    const float* wp2 = (const float*)d_in[11];
    const float* bp2 = (const float*)d_in[12];
    float* out = (float*)d_out;

    cudaFuncSetAttribute(k_cmma, cudaFuncAttributeMaxDynamicSharedMemorySize, CMMA_SMEM);

    k_fused<<<1152, 256>>>(sf, ws, tf, wt, gtw, gtb);    // 0 (search + template)
    k_corr<<<2048, 256>>>(gsw, gsb);                     // 1
    k_tr<<<1024, 256>>>();                               // 2
    k_cmma<<<148, 256, CMMA_SMEM>>>(wp1);                // 3  (ncu capture slot)
    k_out<<<512, 256>>>(wp2, bp2, gpw, gpb, out);        // 4
}